// round 14
// baseline (speedup 1.0000x reference)
#include <cuda_runtime.h>
#include <cuda_fp16.h>
#include <cstdint>
#include <math.h>

#define B_ 2
#define S_ 1024
#define HID_ 4096
#define NH_ 32
#define NKV_ 8
#define D_ 128
#define WINDOW_ 512
#define QKV_OUT_ ((NH_ + 2 * NKV_) * D_)   /* 6144 */
#define BS_ (B_ * S_)                      /* 2048 */
#define VSTART_ ((NH_ + NKV_) * D_)        /* 5120 */

/* ------------------------- scratch (static device globals) ---------------- */
__device__ __half g_qh[B_ * NH_ * S_ * D_];
__device__ __half g_ql[B_ * NH_ * S_ * D_];
__device__ __half g_kh[B_ * NKV_ * S_ * D_];
__device__ __half g_kl[B_ * NKV_ * S_ * D_];
__device__ __half g_v [B_ * NKV_ * S_ * D_];

__device__ int8_t g_a1[BS_ * HID_];
__device__ int8_t g_a2[BS_ * HID_];
__device__ int8_t g_w1[QKV_OUT_ * HID_];
__device__ int8_t g_w2[QKV_OUT_ * HID_];
__device__ float  g_sx[BS_];
__device__ float  g_sy[QKV_OUT_];

__device__ __half g_wo_h[HID_ * HID_];
__device__ __half g_at_h[BS_ * HID_];

/* ============================ PTX helpers (base ISA only) ================= */
__device__ __forceinline__ uint32_t smem_u32(const void* p) {
    return (uint32_t)__cvta_generic_to_shared(p);
}
__device__ __forceinline__ void cp_async16(uint32_t dst, const void* src) {
    asm volatile("cp.async.cg.shared.global [%0], [%1], 16;\n"
                 :: "r"(dst), "l"(src));
}
#define CP_COMMIT() asm volatile("cp.async.commit_group;\n" ::: "memory")
#define CP_WAIT(n)  asm volatile("cp.async.wait_group %0;\n" :: "n"(n) : "memory")

__device__ __forceinline__ void ldsm4(uint32_t* r, uint32_t addr) {
    asm volatile("ldmatrix.sync.aligned.m8n8.x4.shared.b16 {%0,%1,%2,%3}, [%4];"
                 : "=r"(r[0]), "=r"(r[1]), "=r"(r[2]), "=r"(r[3]) : "r"(addr));
}
__device__ __forceinline__ void ldsm4t(uint32_t* r, uint32_t addr) {
    asm volatile("ldmatrix.sync.aligned.m8n8.x4.trans.shared.b16 {%0,%1,%2,%3}, [%4];"
                 : "=r"(r[0]), "=r"(r[1]), "=r"(r[2]), "=r"(r[3]) : "r"(addr));
}
__device__ __forceinline__ void mma_h_f32(float* d, const uint32_t* a,
                                          const uint32_t* b) {
    asm volatile("mma.sync.aligned.m16n8k16.row.col.f32.f16.f16.f32 "
                 "{%0,%1,%2,%3}, {%4,%5,%6,%7}, {%8,%9}, {%0,%1,%2,%3};"
                 : "+f"(d[0]), "+f"(d[1]), "+f"(d[2]), "+f"(d[3])
                 : "r"(a[0]), "r"(a[1]), "r"(a[2]), "r"(a[3]),
                   "r"(b[0]), "r"(b[1]));
}
__device__ __forceinline__ void mma_s8(int* d, const uint32_t* a,
                                       const uint32_t* b) {
    asm volatile("mma.sync.aligned.m16n8k32.row.col.s32.s8.s8.s32 "
                 "{%0,%1,%2,%3}, {%4,%5,%6,%7}, {%8,%9}, {%0,%1,%2,%3};"
                 : "+r"(d[0]), "+r"(d[1]), "+r"(d[2]), "+r"(d[3])
                 : "r"(a[0]), "r"(a[1]), "r"(a[2]), "r"(a[3]),
                   "r"(b[0]), "r"(b[1]));
}
__device__ __forceinline__ float ex2f(float x) {
    float y;
    asm("ex2.approx.f32 %0, %1;" : "=f"(y) : "f"(x));
    return y;
}
__device__ __forceinline__ void pack_hilo_h(float x, float y,
                                            uint32_t& hw, uint32_t& lw) {
    __half2 h = __floats2half2_rn(x, y);
    float2 hf = __half22float2(h);
    __half2 l = __floats2half2_rn(x - hf.x, y - hf.y);
    hw = *(uint32_t*)&h;
    lw = *(uint32_t*)&l;
}
__device__ __forceinline__ uint32_t pack_h(float x, float y) {
    __half2 h = __floats2half2_rn(x, y);
    return *(uint32_t*)&h;
}

/* ============ row-wise fp32 -> 2x int8 quantization (14-bit) ============== */
/* one block per row of ncols (=4096) floats */
__global__ void __launch_bounds__(256) quant_rows(
    const float* __restrict__ x, int8_t* __restrict__ q1,
    int8_t* __restrict__ q2, float* __restrict__ sc, int ncols)
{
    const int row = blockIdx.x;
    const int tid = threadIdx.x;
    const float* xr = x + (size_t)row * ncols;
    __shared__ float red[32];

    float amax = 0.f;
    for (int c = tid * 4; c < ncols; c += 1024) {
        float4 v = *(const float4*)(xr + c);
        amax = fmaxf(amax, fmaxf(fmaxf(fabsf(v.x), fabsf(v.y)),
                                 fmaxf(fabsf(v.z), fabsf(v.w))));
    }
#pragma unroll
    for (int o = 16; o > 0; o >>= 1)
        amax = fmaxf(amax, __shfl_xor_sync(0xffffffffu, amax, o));
    if ((tid & 31) == 0) red[tid >> 5] = amax;
    __syncthreads();
    if (tid < 32) {
        float v = (tid < 8) ? red[tid] : 0.f;
#pragma unroll
        for (int o = 4; o > 0; o >>= 1)
            v = fmaxf(v, __shfl_xor_sync(0xffffffffu, v, o));
        if (tid == 0) red[0] = v;
    }
    __syncthreads();
    amax = red[0];
    const float s   = amax * (1.f / 127.f);
    const float inv = (amax > 0.f) ? (127.f / amax) : 0.f;
    if (tid == 0) sc[row] = s;

    int8_t* q1r = q1 + (size_t)row * ncols;
    int8_t* q2r = q2 + (size_t)row * ncols;
    for (int c = tid * 4; c < ncols; c += 1024) {
        float4 v = *(const float4*)(xr + c);
        float t0 = v.x * inv, t1 = v.y * inv, t2 = v.z * inv, t3 = v.w * inv;
        float a0 = rintf(t0), a1 = rintf(t1), a2 = rintf(t2), a3 = rintf(t3);
        float r0 = (t0 - a0) * 256.f, r1 = (t1 - a1) * 256.f;
        float r2 = (t2 - a2) * 256.f, r3 = (t3 - a3) * 256.f;
        r0 = fminf(fmaxf(rintf(r0), -127.f), 127.f);
        r1 = fminf(fmaxf(rintf(r1), -127.f), 127.f);
        r2 = fminf(fmaxf(rintf(r2), -127.f), 127.f);
        r3 = fminf(fmaxf(rintf(r3), -127.f), 127.f);
        char4 c1 = {(char)(int)a0, (char)(int)a1, (char)(int)a2, (char)(int)a3};
        char4 c2 = {(char)(int)r0, (char)(int)r1, (char)(int)r2, (char)(int)r3};
        *(char4*)(q1r + c) = c1;
        *(char4*)(q2r + c) = c2;
    }
}

/* ==================== fp32 -> fp16 (hi only) ============================== */
__global__ void cvt_h(const float* __restrict__ x,
                      __half* __restrict__ hi, int n4)
{
    int i = blockIdx.x * blockDim.x + threadIdx.x;
    if (i >= n4) return;
    float4 v = ((const float4*)x)[i];
    uint2 hw;
    hw.x = pack_h(v.x, v.y);
    hw.y = pack_h(v.z, v.w);
    ((uint2*)hi)[i] = hw;
}

/* ============== GEMM1: int8 3-product (IMMA k32), fused RoPE ============== */
/* CTA 128x128, 16 warps (4x4 of 32x32 warp tiles), K-tile 64 int8, 3 stages.
   Per k32 step: p_hi += a1*b1 ; p_mid += a1*b2 + a2*b1 (s32, exact).
   value = sx*sy*(p_hi + p_mid/256). Epilogue: Q/K RoPE+fp16 hi/lo, V fp16. */
#define I8_SA1 0
#define I8_SA2 10240
#define I8_SB1 20480
#define I8_SB2 30720
#define I8_STAGE_B 40960
#define I8_STAGES 3
#define I8_SMEM (I8_STAGES * I8_STAGE_B)    /* 122880 B */
#define I8_CP 132

__global__ void __launch_bounds__(512, 1) gemm1_i8(
    const int8_t* __restrict__ A1, const int8_t* __restrict__ A2,
    const int8_t* __restrict__ W1, const int8_t* __restrict__ W2,
    const float* __restrict__ bias,
    const float* __restrict__ cosp, const float* __restrict__ sinp,
    int K)
{
    extern __shared__ char ismem[];
    const uint32_t sb = smem_u32(ismem);

    const int tid  = threadIdx.x;
    const int lane = tid & 31;
    const int wid  = tid >> 5;
    const int wy   = wid >> 2;          /* 0..3 : 32-row band */
    const int wx   = wid & 3;           /* 0..3 : 32-col band */
    const int m0   = blockIdx.y * 128;
    const int n0   = blockIdx.x * 128;
    const int KT   = K / 64;

    /* loader: 512 threads, one 16B chunk per plane: row=tid>>2, chunk=tid&3 */
    const int lr = tid >> 2;
    const int lc = (tid & 3) * 16;
    const uint32_t doff = (uint32_t)(lr * 80 + lc);

    int hi[2][4][4], md[2][4][4];
#pragma unroll
    for (int mt = 0; mt < 2; mt++)
#pragma unroll
        for (int nt = 0; nt < 4; nt++)
#pragma unroll
            for (int j = 0; j < 4; j++) { hi[mt][nt][j] = 0; md[mt][nt][j] = 0; }

    const uint32_t a_off = (uint32_t)((wy * 32 + (lane & 15)) * 80 +
                                      (lane >> 4) * 16);
    const uint32_t b_off = (uint32_t)((wx * 32 + ((lane >> 4) << 3) +
                                       (lane & 7)) * 80 +
                                      ((lane >> 3) & 1) * 16);

#define I8_LOAD(kt, st) do {                                               \
        const int k0_ = (kt) * 64;                                         \
        const uint32_t s0_ = sb + (st) * I8_STAGE_B + doff;                \
        size_t asrc_ = (size_t)(m0 + lr) * K + k0_ + lc;                   \
        size_t bsrc_ = (size_t)(n0 + lr) * K + k0_ + lc;                   \
        cp_async16(s0_ + I8_SA1, A1 + asrc_);                              \
        cp_async16(s0_ + I8_SA2, A2 + asrc_);                              \
        cp_async16(s0_ + I8_SB1, W1 + bsrc_);                              \
        cp_async16(s0_ + I8_SB2, W2 + bsrc_);                              \
    } while (0)

    I8_LOAD(0, 0); CP_COMMIT();
    I8_LOAD(1, 1); CP_COMMIT();

    int st = 0;
    for (int kt = 0; kt < KT; kt++) {
        if (kt + 1 < KT) { CP_WAIT(1); } else { CP_WAIT(0); }
        __syncthreads();
        if (kt + 2 < KT) {
            int st2 = st + 2; if (st2 >= I8_STAGES) st2 -= I8_STAGES;
            I8_LOAD(kt + 2, st2);
            CP_COMMIT();
        }

        const uint32_t stb = sb + st * I8_STAGE_B;
#pragma unroll
        for (int ks = 0; ks < 2; ks++) {
            const uint32_t kso = (uint32_t)ks * 32;
            uint32_t b1[4][2], b2[4][2];
#pragma unroll
            for (int nb = 0; nb < 2; nb++) {
                uint32_t bo = stb + b_off + (uint32_t)(nb * 16 * 80) + kso;
                uint32_t r[4];
                ldsm4(r, bo + I8_SB1);
                b1[nb * 2][0] = r[0]; b1[nb * 2][1] = r[1];
                b1[nb * 2 + 1][0] = r[2]; b1[nb * 2 + 1][1] = r[3];
                ldsm4(r, bo + I8_SB2);
                b2[nb * 2][0] = r[0]; b2[nb * 2][1] = r[1];
                b2[nb * 2 + 1][0] = r[2]; b2[nb * 2 + 1][1] = r[3];
            }
#pragma unroll
            for (int mt = 0; mt < 2; mt++) {
                uint32_t a1[4], a2[4];
                uint32_t ao = stb + a_off + (uint32_t)(mt * 16 * 80) + kso;
                ldsm4(a1, ao + I8_SA1);
                ldsm4(a2, ao + I8_SA2);
#pragma unroll
                for (int nt = 0; nt < 4; nt++)
                    mma_s8(hi[mt][nt], a1, b1[nt]);
#pragma unroll
                for (int nt = 0; nt < 4; nt++)
                    mma_s8(md[mt][nt], a1, b2[nt]);
#pragma unroll
                for (int nt = 0; nt < 4; nt++)
                    mma_s8(md[mt][nt], a2, b1[nt]);
            }
        }
        st++; if (st >= I8_STAGES) st -= I8_STAGES;
    }
#undef I8_LOAD

    /* stage combined fp32 into smem, then scale+bias+RoPE epilogue */
    __syncthreads();
    float* sC = (float*)ismem;
#pragma unroll
    for (int mt = 0; mt < 2; mt++) {
        int r0 = wy * 32 + mt * 16 + (lane >> 2);
#pragma unroll
        for (int nt = 0; nt < 4; nt++) {
            int cl = wx * 32 + nt * 8 + (lane & 3) * 2;
            float v0 = (float)hi[mt][nt][0] + (float)md[mt][nt][0] * 0.00390625f;
            float v1 = (float)hi[mt][nt][1] + (float)md[mt][nt][1] * 0.00390625f;
            float v2 = (float)hi[mt][nt][2] + (float)md[mt][nt][2] * 0.00390625f;
            float v3 = (float)hi[mt][nt][3] + (float)md[mt][nt][3] * 0.00390625f;
            *(float2*)&sC[r0 * I8_CP + cl]       = make_float2(v0, v1);
            *(float2*)&sC[(r0 + 8) * I8_CP + cl] = make_float2(v2, v3);
        }
    }
    __syncthreads();

    const float SCALE = 0.08838834764831845f;
    for (int e = tid; e < 4096; e += 512) {
        int i = e & 31;
        int r = e >> 5;
        int d0 = 2 * i;
        int row = m0 + r;
        int bb = row >> 10, s = row & 1023;
        float sxr = g_sx[row];

        int c0 = n0 + d0, c2 = n0 + 64 + d0;
        float2 raw_lo = *(float2*)&sC[r * I8_CP + d0];
        float2 raw_hi = *(float2*)&sC[r * I8_CP + 64 + d0];
        float vlo0 = raw_lo.x * sxr * g_sy[c0]     + bias[c0];
        float vlo1 = raw_lo.y * sxr * g_sy[c0 + 1] + bias[c0 + 1];
        float vhi0 = raw_hi.x * sxr * g_sy[c2]     + bias[c2];
        float vhi1 = raw_hi.y * sxr * g_sy[c2 + 1] + bias[c2 + 1];

        if (n0 < NH_ * D_) {
            float2 c_lo = *(const float2*)&cosp[s * D_ + d0];
            float2 c_hi = *(const float2*)&cosp[s * D_ + 64 + d0];
            float2 s_lo = *(const float2*)&sinp[s * D_ + d0];
            float2 s_hi = *(const float2*)&sinp[s * D_ + 64 + d0];
            int h = n0 >> 7;
            float o0 = (vlo0 * c_lo.x - vhi0 * s_lo.x) * SCALE;
            float o1 = (vlo1 * c_lo.y - vhi1 * s_lo.y) * SCALE;
            float o2 = (vhi0 * c_hi.x + vlo0 * s_hi.x) * SCALE;
            float o3 = (vhi1 * c_hi.y + vlo1 * s_hi.y) * SCALE;
            size_t base = (((size_t)bb * NH_ + h) * S_ + s) * D_;
            uint32_t hw, lw;
            pack_hilo_h(o0, o1, hw, lw);
            *(uint32_t*)(g_qh + base + d0) = hw;
            *(uint32_t*)(g_ql + base + d0) = lw;
            pack_hilo_h(o2, o3, hw, lw);
            *(uint32_t*)(g_qh + base + 64 + d0) = hw;
            *(uint32_t*)(g_ql + base + 64 + d0) = lw;
        } else if (n0 < VSTART_) {
            float2 c_lo = *(const float2*)&cosp[s * D_ + d0];
            float2 c_hi = *(const float2*)&cosp[s * D_ + 64 + d0];
            float2 s_lo = *(const float2*)&sinp[s * D_ + d0];
            float2 s_hi = *(const float2*)&sinp[s * D_ + 64 + d0];
            int kvh = (n0 - NH_ * D_) >> 7;
            float o0 = vlo0 * c_lo.x - vhi0 * s_lo.x;
            float o1 = vlo1 * c_lo.y - vhi1 * s_lo.y;
            float o2 = vhi0 * c_hi.x + vlo0 * s_hi.x;
            float o3 = vhi1 * c_hi.y + vlo1 * s_hi.y;
            size_t base = (((size_t)bb * NKV_ + kvh) * S_ + s) * D_;
            uint32_t hw, lw;
            pack_hilo_h(o0, o1, hw, lw);
            *(uint32_t*)(g_kh + base + d0) = hw;
            *(uint32_t*)(g_kl + base + d0) = lw;
            pack_hilo_h(o2, o3, hw, lw);
            *(uint32_t*)(g_kh + base + 64 + d0) = hw;
            *(uint32_t*)(g_kl + base + 64 + d0) = lw;
        } else {
            int kvh = (n0 - VSTART_) >> 7;
            size_t base = (((size_t)bb * NKV_ + kvh) * S_ + s) * D_;
            *(uint32_t*)(g_v + base + d0)      = pack_h(vlo0, vlo1);
            *(uint32_t*)(g_v + base + 64 + d0) = pack_h(vhi0, vhi1);
        }
    }
}

/* ============== GEMM2: single-product fp16, f32 accum ===================== */
#define H1_SA 0
#define H1_SB (128 * 40)
#define H1_STAGE_E (384 * 40)
#define H1_STAGE_B (H1_STAGE_E * 2)
#define H1_STAGES 4
#define H1_SMEM (H1_STAGES * H1_STAGE_B)    /* 122880 B */

__global__ void __launch_bounds__(512, 1) gemm_h1(
    const __half* __restrict__ Ah, const __half* __restrict__ Bh,
    const float* __restrict__ bias, float* __restrict__ C, int N, int K)
{
    extern __shared__ __half hsmem[];
    const uint32_t sb = smem_u32(hsmem);

    const int tid  = threadIdx.x;
    const int lane = tid & 31;
    const int wid  = tid >> 5;
    const int wy   = wid >> 3;
    const int wx   = wid & 7;
    const int m0   = blockIdx.y * 128;
    const int n0   = blockIdx.x * 256;
    const int KT   = K / 32;

    const int lr = tid >> 2;
    const int lc = (tid & 3) * 8;
    const uint32_t doff = (uint32_t)(lr * 40 + lc) * 2;

    float acc[4][4][4];
#pragma unroll
    for (int mt = 0; mt < 4; mt++)
#pragma unroll
        for (int nt = 0; nt < 4; nt++)
#pragma unroll
            for (int j = 0; j < 4; j++) acc[mt][nt][j] = 0.f;

    const int a_row = wy * 64 + (lane & 15);
    const int a_col = (lane >> 4) * 8;
    const uint32_t a_off = (uint32_t)(a_row * 40 + a_col) * 2;
    const int b_row = wx * 32 + ((lane >> 4) << 3) + (lane & 7);
    const int b_col = ((lane >> 3) & 1) * 8;
    const uint32_t b_off = (uint32_t)(b_row * 40 + b_col) * 2;

#define H1_LOAD(kt, st) do {                                              \
        const int k0_ = (kt) * 32;                                        \
        const uint32_t s0_ = sb + (st) * H1_STAGE_B + doff;               \
        size_t asrc_ = (size_t)(m0 + lr) * K + k0_ + lc;                  \
        cp_async16(s0_ + H1_SA * 2, Ah + asrc_);                          \
        _Pragma("unroll")                                                 \
        for (int p_ = 0; p_ < 2; p_++) {                                  \
            size_t bsrc_ = (size_t)(n0 + p_ * 128 + lr) * K + k0_ + lc;   \
            cp_async16(s0_ + (H1_SB + p_ * 128 * 40) * 2, Bh + bsrc_);    \
        }                                                                 \
    } while (0)

    H1_LOAD(0, 0); CP_COMMIT();
    H1_LOAD(1, 1); CP_COMMIT();
    H1_LOAD(2, 2); CP_COMMIT();

    int st = 0;
    for (int kt = 0; kt < KT; kt++) {
        if (kt + 2 < KT)      { CP_WAIT(2); }
        else if (kt + 1 < KT) { CP_WAIT(1); }
        else                  { CP_WAIT(0); }
        __syncthreads();
        if (kt + 3 < KT) {
            int st3 = st + 3; if (st3 >= H1_STAGES) st3 -= H1_STAGES;
            H1_LOAD(kt + 3, st3);
            CP_COMMIT();
        }

        const uint32_t stb = sb + st * H1_STAGE_B;
#pragma unroll
        for (int ks = 0; ks < 32; ks += 16) {
            const uint32_t kso = (uint32_t)ks * 2;
            uint32_t bh[4][2];
#pragma unroll
            for (int nt2 = 0; nt2 < 2; nt2++) {
                uint32_t bo = stb + (H1_SB * 2) + b_off +
                              (uint32_t)(nt2 * 16 * 40) * 2 + kso;
                uint32_t r[4];
                ldsm4(r, bo);
                bh[nt2 * 2][0] = r[0]; bh[nt2 * 2][1] = r[1];
                bh[nt2 * 2 + 1][0] = r[2]; bh[nt2 * 2 + 1][1] = r[3];
            }
#pragma unroll
            for (int mt = 0; mt < 4; mt++) {
                uint32_t ah[4];
                uint32_t ao = stb + a_off + (uint32_t)(mt * 16 * 40) * 2 + kso;
                ldsm4(ah, ao);
#pragma unroll
                for (int nt = 0; nt < 4; nt++)
                    mma_h_f32(acc[mt][nt], ah, bh[nt]);
            }
        }
        st++; if (st >= H1_STAGES) st -= H1_STAGES;
    }
#undef H1_LOAD

#pragma unroll
    for (int mt = 0; mt < 4; mt++) {
        int row0 = m0 + wy * 64 + mt * 16 + (lane >> 2);
#pragma unroll
        for (int nt = 0; nt < 4; nt++) {
            int col = n0 + wx * 32 + nt * 8 + (lane & 3) * 2;
            float b0 = bias[col], b1 = bias[col + 1];
            float2 v0 = {acc[mt][nt][0] + b0, acc[mt][nt][1] + b1};
            float2 v1 = {acc[mt][nt][2] + b0, acc[mt][nt][3] + b1};
            *(float2*)(C + (size_t)row0 * N + col)       = v0;
            *(float2*)(C + (size_t)(row0 + 8) * N + col) = v1;
        }
    }
}

/* ============ HMMA flash attention: QK fp16x3, PV fp16x1 ================== */
#define AT_PAD 136
#define AQ_L   (128 * AT_PAD)
#define AST0   (2 * 128 * AT_PAD)
#define AMAT   (64 * AT_PAD)
#define ASTAGE (3 * AMAT)
#define ATTN_SMEM_B ((AST0 + 2 * ASTAGE) * 2)   /* 174080 B */
#define LOG2E 1.4426950408889634f

__global__ void __launch_bounds__(256, 1) attn_mma()
{
    const int qbx = blockIdx.x, h = blockIdx.y, b = blockIdx.z;
    const int kvh = h >> 2;
    const int qlo = qbx * 128;

    extern __shared__ __half asmem[];
    const uint32_t sb = smem_u32(asmem);
    const int tid = threadIdx.x, lane = tid & 31, w = tid >> 5;

    const __half* Qhg = g_qh + (((size_t)b * NH_ + h) * S_ + qlo) * D_;
    const __half* Qlg = g_ql + (((size_t)b * NH_ + h) * S_ + qlo) * D_;
    const __half* Khg = g_kh + ((size_t)b * NKV_ + kvh) * S_ * D_;
    const __half* Klg = g_kl + ((size_t)b * NKV_ + kvh) * S_ * D_;
    const __half* Vg  = g_v  + ((size_t)b * NKV_ + kvh) * S_ * D_;

    for (int c = tid; c < 2048; c += 256) {
        int row = c >> 4, ch = c & 15;
        uint32_t dq = sb + (uint32_t)(row * AT_PAD + ch * 8) * 2;
        size_t src = (size_t)row * D_ + ch * 8;
        cp_async16(dq, Qhg + src);
        cp_async16(dq + AQ_L * 2, Qlg + src);
    }

#define LOAD_KV(kb, st) do {                                            \
        const int kbase_ = (kb) * 64;                                   \
        const uint32_t s0_ = sb + (uint32_t)(AST0 + (st) * ASTAGE) * 2; \
        for (int c = tid; c < 1024; c += 256) {                         \
            int row_ = c >> 4, ch_ = c & 15;                            \
            uint32_t d_ = s0_ + (uint32_t)(row_ * AT_PAD + ch_ * 8) * 2;\
            size_t src_ = (size_t)(kbase_ + row_) * D_ + ch_ * 8;       \
            cp_async16(d_,                Khg + src_);                  \
            cp_async16(d_ + AMAT * 2,     Klg + src_);                  \
            cp_async16(d_ + 2 * AMAT * 2, Vg  + src_);                  \
        } } while (0)

    int kstart = qlo - (WINDOW_ - 1);
    if (kstart < 0) kstart = 0;
    const int kb0 = kstart >> 6;
    const int kb1 = (qlo + 127) >> 6;

    LOAD_KV(kb0, 0);
    CP_COMMIT();

    float oacc[16][4];
#pragma unroll
    for (int nf = 0; nf < 16; nf++)
#pragma unroll
        for (int j = 0; j < 4; j++) oacc[nf][j] = 0.f;
    float m0 = -1e30f, m1 = -1e30f, l0 = 0.f, l1 = 0.f;

    const int qg0 = qlo + w * 16 + (lane >> 2);
    const int qg1 = qg0 + 8;
    const uint32_t qrow_off =
        (uint32_t)((w * 16 + (lane & 15)) * AT_PAD + (lane >> 4) * 8) * 2;
    const uint32_t krow_off =
        (uint32_t)((((lane >> 4) << 3) + (lane & 7)) * AT_PAD +
                   ((lane >> 3) & 1) * 8) * 2;
    const uint32_t vrow_off =
        (uint32_t)((lane & 15) * AT_PAD + (lane >> 4) * 8) * 2;

    for (int kb = kb0; kb <= kb1; kb++) {
        const int st = (kb - kb0) & 1;
        if (kb < kb1) {
            LOAD_KV(kb + 1, st ^ 1);
            CP_COMMIT();
            CP_WAIT(1);
        } else {
            CP_WAIT(0);
        }
        __syncthreads();

        const uint32_t stb = sb + (uint32_t)(AST0 + st * ASTAGE) * 2;
        const int kbase = kb * 64;

        float sacc[8][4];
#pragma unroll
        for (int j = 0; j < 8; j++)
#pragma unroll
            for (int i = 0; i < 4; i++) sacc[j][i] = 0.f;

#pragma unroll
        for (int kk = 0; kk < 8; kk++) {
            uint32_t qh[4], ql[4];
            const uint32_t qoff = sb + qrow_off + kk * 32;
            ldsm4(qh, qoff);
            ldsm4(ql, qoff + AQ_L * 2);
#pragma unroll
            for (int nb = 0; nb < 4; nb++) {
                uint32_t kh[4], kl[4];
                const uint32_t koff = stb + krow_off +
                    (uint32_t)(nb * 16 * AT_PAD) * 2 + kk * 32;
                ldsm4(kh, koff);
                ldsm4(kl, koff + AMAT * 2);
                mma_h_f32(sacc[2 * nb],     qh, kh);
                mma_h_f32(sacc[2 * nb],     qh, kl);
                mma_h_f32(sacc[2 * nb],     ql, kh);
                mma_h_f32(sacc[2 * nb + 1], qh, &kh[2]);
                mma_h_f32(sacc[2 * nb + 1], qh, &kl[2]);
                mma_h_f32(sacc[2 * nb + 1], ql, &kh[2]);
            }
        }

#pragma unroll
        for (int j = 0; j < 8; j++) {
            const int kg0 = kbase + 8 * j + 2 * (lane & 3);
            const int kg1 = kg0 + 1;
            if (!(kg0 <= qg0 && qg0 - kg0 < WINDOW_)) sacc[j][0] = -1e30f;
            if (!(kg1 <= qg0 && qg0 - kg1 < WINDOW_)) sacc[j][1] = -1e30f;
            if (!(kg0 <= qg1 && qg1 - kg0 < WINDOW_)) sacc[j][2] = -1e30f;
            if (!(kg1 <= qg1 && qg1 - kg1 < WINDOW_)) sacc[j][3] = -1e30f;
        }

        float mx0 = m0, mx1 = m1;
#pragma unroll
        for (int j = 0; j < 8; j++) {
            mx0 = fmaxf(mx0, fmaxf(sacc[j][0], sacc[j][1]));
            mx1 = fmaxf(mx1, fmaxf(sacc[j][2], sacc[j][3]));
        }
        mx0 = fmaxf(mx0, __shfl_xor_sync(0xffffffffu, mx0, 1));
        mx0 = fmaxf(mx0, __shfl_xor_sync(0xffffffffu, mx0, 2));
        mx1 = fmaxf(mx1, __shfl_xor_sync(0xffffffffu, mx1, 1));
        mx1 = fmaxf(mx1, __shfl_xor_sync(0xffffffffu, mx1, 2));

        const float sc0 = ex2f((m0 - mx0) * LOG2E);
        const float sc1 = ex2f((m1 - mx1) * LOG2E);
        float la0 = 0.f, la1 = 0.f;
#pragma unroll
        for (int j = 0; j < 8; j++) {
            float p0 = (sacc[j][0] > -1e29f) ? ex2f((sacc[j][0] - mx0) * LOG2E) : 0.f;
            float p1 = (sacc[j][1] > -1e29f) ? ex2f((sacc[j][1] - mx0) * LOG2E) : 0.f;
            float p2 = (sacc[j][2] > -1e29f) ? ex2f((sacc[j][2] - mx1) * LOG2E) : 0.f;
            float p3 = (sacc[j][3] > -1e29f) ? ex2f((sacc[j][3] - mx1) * LOG2E) : 0.f;
            sacc[j][0] = p0; sacc[j][1] = p1; sacc[j][2] = p2; sacc[j][3] = p3;
            la0 += p0 + p1;
            la1 += p2 + p3;
        }
        la0 += __shfl_xor_sync(0xffffffffu, la0, 1);
        la0 += __shfl_xor_sync(0xffffffffu, la0, 2);
        la1 += __shfl_xor_sync(0xffffffffu, la1, 1);
        la1 += __shfl_xor_sync(0xffffffffu, la1, 2);
        l0 = l0 * sc0 + la0;
        l1 = l1 * sc1 + la1;
        m0 = mx0; m1 = mx1;

#pragma unroll
        for (int nf = 0; nf < 16; nf++) {
            oacc[nf][0] *= sc0; oacc[nf][1] *= sc0;
            oacc[nf][2] *= sc1; oacc[nf][3] *= sc1;
        }

#pragma unroll
        for (int s4 = 0; s4 < 4; s4++) {
            uint32_t ah[4];
            ah[0] = pack_h(sacc[2 * s4][0],     sacc[2 * s4][1]);
            ah[1] = pack_h(sacc[2 * s4][2],     sacc[2 * s4][3]);
            ah[2] = pack_h(sacc[2 * s4 + 1][0], sacc[2 * s4 + 1][1]);
            ah[3] = pack_h(sacc[2 * s4 + 1][2], sacc[2 * s4 + 1][3]);

            const uint32_t vbase = stb + 2 * AMAT * 2 + vrow_off +
                                   (uint32_t)(s4 * 16 * AT_PAD) * 2;
#pragma unroll
            for (int db = 0; db < 8; db++) {
                uint32_t vh[4];
                ldsm4t(vh, vbase + db * 32);
                mma_h_f32(oacc[2 * db],     ah, vh);
                mma_h_f32(oacc[2 * db + 1], ah, &vh[2]);
            }
        }
        __syncthreads();
    }
#undef LOAD_KV

    const float inv0 = 1.f / l0;
    const float inv1 = 1.f / l1;
    const size_t o0 = (size_t)(b * S_ + qg0) * (NH_ * D_) + h * D_;
    const size_t o1 = (size_t)(b * S_ + qg1) * (NH_ * D_) + h * D_;
#pragma unroll
    for (int nf = 0; nf < 16; nf++) {
        const int dc = 8 * nf + 2 * (lane & 3);
        *(uint32_t*)(g_at_h + o0 + dc) =
            pack_h(oacc[nf][0] * inv0, oacc[nf][1] * inv0);
        *(uint32_t*)(g_at_h + o1 + dc) =
            pack_h(oacc[nf][2] * inv1, oacc[nf][3] * inv1);
    }
}

/* --------------------------------- launch --------------------------------- */
extern "C" void kernel_launch(void* const* d_in, const int* in_sizes, int n_in,
                              void* d_out, int out_size)
{
    const float* hidden = (const float*)d_in[0];
    const float* cosp   = (const float*)d_in[1];
    const float* sinp   = (const float*)d_in[2];
    const float* w_qkv  = (const float*)d_in[3];
    const float* b_qkv  = (const float*)d_in[4];
    const float* w_o    = (const float*)d_in[5];
    const float* b_o    = (const float*)d_in[6];
    float* out = (float*)d_out;

    int8_t *p_a1, *p_a2, *p_w1, *p_w2;
    float *p_sx, *p_sy;
    __half *p_wo_h, *p_at_h;
    cudaGetSymbolAddress((void**)&p_a1, g_a1);
    cudaGetSymbolAddress((void**)&p_a2, g_a2);
    cudaGetSymbolAddress((void**)&p_w1, g_w1);
    cudaGetSymbolAddress((void**)&p_w2, g_w2);
    cudaGetSymbolAddress((void**)&p_sx, g_sx);
    cudaGetSymbolAddress((void**)&p_sy, g_sy);
    cudaGetSymbolAddress((void**)&p_wo_h, g_wo_h);
    cudaGetSymbolAddress((void**)&p_at_h, g_at_h);

    cudaFuncSetAttribute(gemm1_i8,
                         cudaFuncAttributeMaxDynamicSharedMemorySize, I8_SMEM);
    cudaFuncSetAttribute(gemm_h1,
                         cudaFuncAttributeMaxDynamicSharedMemorySize, H1_SMEM);
    cudaFuncSetAttribute(attn_mma,
                         cudaFuncAttributeMaxDynamicSharedMemorySize, ATTN_SMEM_B);

    /* quantize / convert */
    quant_rows<<<BS_, 256>>>(hidden, p_a1, p_a2, p_sx, HID_);
    quant_rows<<<QKV_OUT_, 256>>>(w_qkv, p_w1, p_w2, p_sy, HID_);
    cvt_h<<<(HID_ * HID_ / 4 + 255) / 256, 256>>>(w_o, p_wo_h, HID_ * HID_ / 4);

    /* 1) qkv GEMM (int8 3-product IMMA) + fused scale/bias/RoPE epilogue */
    gemm1_i8<<<dim3(QKV_OUT_ / 128, BS_ / 128), 512, I8_SMEM>>>(
        p_a1, p_a2, p_w1, p_w2, b_qkv, cosp, sinp, HID_);

    /* 2) flash attention (QK fp16x3, PV fp16x1) */
    attn_mma<<<dim3(S_ / 128, NH_, B_), 256, ATTN_SMEM_B>>>();

    /* 3) out = attn @ w_o^T + b_o (single-product fp16) */
    gemm_h1<<<dim3(HID_ / 256, BS_ / 128), 512, H1_SMEM>>>(
        p_at_h, p_wo_h, b_o, out, HID_, HID_);
}

// round 15
// speedup vs baseline: 2.1663x; 2.1663x over previous
#include <cuda_runtime.h>
#include <cuda_fp16.h>
#include <cstdint>
#include <math.h>

#define B_ 2
#define S_ 1024
#define HID_ 4096
#define NH_ 32
#define NKV_ 8
#define D_ 128
#define WINDOW_ 512
#define QKV_OUT_ ((NH_ + 2 * NKV_) * D_)   /* 6144 */
#define BS_ (B_ * S_)                      /* 2048 */
#define VSTART_ ((NH_ + NKV_) * D_)        /* 5120 */

/* ------------------------- scratch (static device globals) ---------------- */
__device__ __half g_qh[B_ * NH_ * S_ * D_];
__device__ __half g_ql[B_ * NH_ * S_ * D_];
__device__ __half g_kh[B_ * NKV_ * S_ * D_];
__device__ __half g_kl[B_ * NKV_ * S_ * D_];
__device__ __half g_v [B_ * NKV_ * S_ * D_];

__device__ __half g_h_hi[BS_ * HID_];
__device__ __half g_h_lo[BS_ * HID_];
__device__ __half g_wq_hi[QKV_OUT_ * HID_];
__device__ __half g_wq_lo[QKV_OUT_ * HID_];
__device__ __half g_wo_h[HID_ * HID_];
__device__ __half g_at_h[BS_ * HID_];

/* ============================ PTX helpers (base ISA only) ================= */
__device__ __forceinline__ uint32_t smem_u32(const void* p) {
    return (uint32_t)__cvta_generic_to_shared(p);
}
__device__ __forceinline__ void cp_async16(uint32_t dst, const void* src) {
    asm volatile("cp.async.cg.shared.global [%0], [%1], 16;\n"
                 :: "r"(dst), "l"(src));
}
#define CP_COMMIT() asm volatile("cp.async.commit_group;\n" ::: "memory")
#define CP_WAIT(n)  asm volatile("cp.async.wait_group %0;\n" :: "n"(n) : "memory")

__device__ __forceinline__ void ldsm4(uint32_t* r, uint32_t addr) {
    asm volatile("ldmatrix.sync.aligned.m8n8.x4.shared.b16 {%0,%1,%2,%3}, [%4];"
                 : "=r"(r[0]), "=r"(r[1]), "=r"(r[2]), "=r"(r[3]) : "r"(addr));
}
__device__ __forceinline__ void ldsm4t(uint32_t* r, uint32_t addr) {
    asm volatile("ldmatrix.sync.aligned.m8n8.x4.trans.shared.b16 {%0,%1,%2,%3}, [%4];"
                 : "=r"(r[0]), "=r"(r[1]), "=r"(r[2]), "=r"(r[3]) : "r"(addr));
}
__device__ __forceinline__ void mma_h_f32(float* d, const uint32_t* a,
                                          const uint32_t* b) {
    asm volatile("mma.sync.aligned.m16n8k16.row.col.f32.f16.f16.f32 "
                 "{%0,%1,%2,%3}, {%4,%5,%6,%7}, {%8,%9}, {%0,%1,%2,%3};"
                 : "+f"(d[0]), "+f"(d[1]), "+f"(d[2]), "+f"(d[3])
                 : "r"(a[0]), "r"(a[1]), "r"(a[2]), "r"(a[3]),
                   "r"(b[0]), "r"(b[1]));
}
__device__ __forceinline__ float ex2f(float x) {
    float y;
    asm("ex2.approx.f32 %0, %1;" : "=f"(y) : "f"(x));
    return y;
}
__device__ __forceinline__ void pack_hilo_h(float x, float y,
                                            uint32_t& hw, uint32_t& lw) {
    __half2 h = __floats2half2_rn(x, y);
    float2 hf = __half22float2(h);
    __half2 l = __floats2half2_rn(x - hf.x, y - hf.y);
    hw = *(uint32_t*)&h;
    lw = *(uint32_t*)&l;
}
__device__ __forceinline__ uint32_t pack_h(float x, float y) {
    __half2 h = __floats2half2_rn(x, y);
    return *(uint32_t*)&h;
}

/* ==================== fp32 -> fp16 hi/lo split ============================ */
__global__ void cvt_split_h(const float* __restrict__ x,
                            __half* __restrict__ hi,
                            __half* __restrict__ lo, int n4)
{
    int i = blockIdx.x * blockDim.x + threadIdx.x;
    if (i >= n4) return;
    float4 v = ((const float4*)x)[i];
    uint2 hw, lw;
    uint32_t a, b;
    pack_hilo_h(v.x, v.y, a, b); hw.x = a; lw.x = b;
    pack_hilo_h(v.z, v.w, a, b); hw.y = a; lw.y = b;
    ((uint2*)hi)[i] = hw;
    ((uint2*)lo)[i] = lw;
}

/* ==================== fp32 -> fp16 (hi only) ============================== */
__global__ void cvt_h(const float* __restrict__ x,
                      __half* __restrict__ hi, int n4)
{
    int i = blockIdx.x * blockDim.x + threadIdx.x;
    if (i >= n4) return;
    float4 v = ((const float4*)x)[i];
    uint2 hw;
    hw.x = pack_h(v.x, v.y);
    hw.y = pack_h(v.z, v.w);
    ((uint2*)hi)[i] = hw;
}

/* ============== GEMM1: dual-path (QK fp16x3 + RoPE | V fp16x1) =========== */
/* CTA-uniform branch on column band. CTA 128x256, 16 warps (2x8 of 64x32),
   BK=32, 3-stage ring. QK path identical to R13. V path: 1 product.        */
#define SA_HI 0
#define SA_LO (128 * 40)
#define SB_HI (2 * 128 * 40)
#define SB_LO (2 * 128 * 40 + 256 * 40)
#define GSTAGE_E (2 * 128 * 40 + 2 * 256 * 40)
#define GSTAGE_B (GSTAGE_E * 2)
#define GSTAGES 3
#define GSMEM (GSTAGES * GSTAGE_B)                 /* 184320 B */
#define CPITCH 260

__global__ void __launch_bounds__(512, 1) gemm1_u(
    const __half* __restrict__ Ah, const __half* __restrict__ Al,
    const __half* __restrict__ Bh, const __half* __restrict__ Bl,
    const float* __restrict__ bias,
    const float* __restrict__ cosp, const float* __restrict__ sinp,
    int K)
{
    extern __shared__ __half smem[];
    const uint32_t sb = smem_u32(smem);

    const int tid  = threadIdx.x;
    const int lane = tid & 31;
    const int wid  = tid >> 5;
    const int wy   = wid >> 3;
    const int wx   = wid & 7;
    const int m0   = blockIdx.y * 128;
    const int n0   = blockIdx.x * 256;
    const int KT   = K / 32;

    const int lr = tid >> 2;
    const int lc = (tid & 3) * 8;
    const uint32_t doff = (uint32_t)(lr * 40 + lc) * 2;

    const uint32_t a_off = (uint32_t)((wy * 64 + (lane & 15)) * 40 +
                                      (lane >> 4) * 8) * 2;
    const uint32_t b_off = (uint32_t)((wx * 32 + ((lane >> 4) << 3) +
                                       (lane & 7)) * 40 +
                                      ((lane >> 3) & 1) * 8) * 2;

    if (n0 >= VSTART_) {
        /* ---------------- V path: single product ------------------------ */
        float acc[4][4][4];
#pragma unroll
        for (int mt = 0; mt < 4; mt++)
#pragma unroll
            for (int nt = 0; nt < 4; nt++)
#pragma unroll
                for (int j = 0; j < 4; j++) acc[mt][nt][j] = 0.f;

#define V_LOAD(kt, st) do {                                                \
        const int k0_ = (kt) * 32;                                         \
        const uint32_t s0_ = sb + (st) * GSTAGE_B + doff;                  \
        size_t asrc_ = (size_t)(m0 + lr) * K + k0_ + lc;                   \
        cp_async16(s0_ + SA_HI * 2, Ah + asrc_);                           \
        _Pragma("unroll")                                                  \
        for (int p_ = 0; p_ < 2; p_++) {                                   \
            size_t bsrc_ = (size_t)(n0 + p_ * 128 + lr) * K + k0_ + lc;    \
            cp_async16(s0_ + SB_HI * 2 + (uint32_t)(p_ * 128 * 40) * 2,    \
                       Bh + bsrc_);                                        \
        }                                                                  \
    } while (0)

        V_LOAD(0, 0); CP_COMMIT();
        V_LOAD(1, 1); CP_COMMIT();

        int st = 0;
        for (int kt = 0; kt < KT; kt++) {
            if (kt + 1 < KT) { CP_WAIT(1); } else { CP_WAIT(0); }
            __syncthreads();
            if (kt + 2 < KT) {
                int st2 = st + 2; if (st2 >= GSTAGES) st2 -= GSTAGES;
                V_LOAD(kt + 2, st2);
                CP_COMMIT();
            }

            const uint32_t stb = sb + st * GSTAGE_B;
#pragma unroll
            for (int ks = 0; ks < 32; ks += 16) {
                const uint32_t kso = (uint32_t)ks * 2;
                uint32_t bh[4][2];
#pragma unroll
                for (int nt2 = 0; nt2 < 2; nt2++) {
                    uint32_t bo = stb + b_off +
                                  (uint32_t)(nt2 * 16 * 40) * 2 + kso;
                    uint32_t r[4];
                    ldsm4(r, bo + SB_HI * 2);
                    bh[nt2 * 2][0] = r[0]; bh[nt2 * 2][1] = r[1];
                    bh[nt2 * 2 + 1][0] = r[2]; bh[nt2 * 2 + 1][1] = r[3];
                }
#pragma unroll
                for (int mt = 0; mt < 4; mt++) {
                    uint32_t ah[4];
                    uint32_t ao = stb + a_off +
                                  (uint32_t)(mt * 16 * 40) * 2 + kso;
                    ldsm4(ah, ao + SA_HI * 2);
#pragma unroll
                    for (int nt = 0; nt < 4; nt++)
                        mma_h_f32(acc[mt][nt], ah, bh[nt]);
                }
            }
            st++; if (st >= GSTAGES) st -= GSTAGES;
        }
#undef V_LOAD

        /* V epilogue: fp16 to g_v[b,kv,s,d] with bias (direct, no smem) */
#pragma unroll
        for (int mt = 0; mt < 4; mt++) {
            int row0 = m0 + wy * 64 + mt * 16 + (lane >> 2);
            int bb0 = row0 >> 10, s0r = row0 & 1023;
            int row1 = row0 + 8;
            int bb1 = row1 >> 10, s1r = row1 & 1023;
#pragma unroll
            for (int nt = 0; nt < 4; nt++) {
                int col = n0 + wx * 32 + nt * 8 + (lane & 3) * 2;
                int kvh = (col - VSTART_) >> 7, d0 = col & 127;
                float b0 = bias[col], b1 = bias[col + 1];
                size_t base0 = (((size_t)bb0 * NKV_ + kvh) * S_ + s0r) * D_ + d0;
                size_t base1 = (((size_t)bb1 * NKV_ + kvh) * S_ + s1r) * D_ + d0;
                *(uint32_t*)(g_v + base0) =
                    pack_h(acc[mt][nt][0] + b0, acc[mt][nt][1] + b1);
                *(uint32_t*)(g_v + base1) =
                    pack_h(acc[mt][nt][2] + b0, acc[mt][nt][3] + b1);
            }
        }
        return;
    }

    /* ---------------- QK path: 3-product + fused RoPE -------------------- */
    float acc[4][4][4];
#pragma unroll
    for (int mt = 0; mt < 4; mt++)
#pragma unroll
        for (int nt = 0; nt < 4; nt++)
#pragma unroll
            for (int j = 0; j < 4; j++) acc[mt][nt][j] = 0.f;

#define LOAD_STAGE(kt, st) do {                                           \
        const int k0_ = (kt) * 32;                                        \
        const uint32_t s0_ = sb + (st) * GSTAGE_B + doff;                 \
        size_t asrc_ = (size_t)(m0 + lr) * K + k0_ + lc;                  \
        cp_async16(s0_ + SA_HI * 2, Ah + asrc_);                          \
        cp_async16(s0_ + SA_LO * 2, Al + asrc_);                          \
        _Pragma("unroll")                                                 \
        for (int p_ = 0; p_ < 2; p_++) {                                  \
            size_t bsrc_ = (size_t)(n0 + p_ * 128 + lr) * K + k0_ + lc;   \
            uint32_t d_ = s0_ + (uint32_t)(p_ * 128 * 40) * 2;            \
            cp_async16(d_ + SB_HI * 2, Bh + bsrc_);                       \
            cp_async16(d_ + SB_LO * 2, Bl + bsrc_);                       \
        }                                                                 \
    } while (0)

    LOAD_STAGE(0, 0);
    CP_COMMIT();
    LOAD_STAGE(1, 1);
    CP_COMMIT();

    int st = 0;
    for (int kt = 0; kt < KT; kt++) {
        if (kt + 1 < KT) { CP_WAIT(1); } else { CP_WAIT(0); }
        __syncthreads();
        if (kt + 2 < KT) {
            int st2 = st + 2; if (st2 >= GSTAGES) st2 -= GSTAGES;
            LOAD_STAGE(kt + 2, st2);
            CP_COMMIT();
        }

        const uint32_t stb = sb + st * GSTAGE_B;
#pragma unroll
        for (int ks = 0; ks < 32; ks += 16) {
            const uint32_t kso = (uint32_t)ks * 2;
            uint32_t bh[4][2], bl[4][2];
#pragma unroll
            for (int nt2 = 0; nt2 < 2; nt2++) {
                uint32_t bo = stb + b_off + (uint32_t)(nt2 * 16 * 40) * 2 + kso;
                uint32_t r[4];
                ldsm4(r, bo + SB_HI * 2);
                bh[nt2 * 2][0] = r[0]; bh[nt2 * 2][1] = r[1];
                bh[nt2 * 2 + 1][0] = r[2]; bh[nt2 * 2 + 1][1] = r[3];
                ldsm4(r, bo + SB_LO * 2);
                bl[nt2 * 2][0] = r[0]; bl[nt2 * 2][1] = r[1];
                bl[nt2 * 2 + 1][0] = r[2]; bl[nt2 * 2 + 1][1] = r[3];
            }
#pragma unroll
            for (int mt = 0; mt < 4; mt++) {
                uint32_t ah[4], al[4];
                uint32_t ao = stb + a_off + (uint32_t)(mt * 16 * 40) * 2 + kso;
                ldsm4(ah, ao + SA_HI * 2);
                ldsm4(al, ao + SA_LO * 2);
#pragma unroll
                for (int nt = 0; nt < 4; nt++)
                    mma_h_f32(acc[mt][nt], ah, bh[nt]);
#pragma unroll
                for (int nt = 0; nt < 4; nt++)
                    mma_h_f32(acc[mt][nt], ah, bl[nt]);
#pragma unroll
                for (int nt = 0; nt < 4; nt++)
                    mma_h_f32(acc[mt][nt], al, bh[nt]);
            }
        }
        st++; if (st >= GSTAGES) st -= GSTAGES;
    }
#undef LOAD_STAGE

    __syncthreads();
    float* sC = (float*)smem;
#pragma unroll
    for (int mt = 0; mt < 4; mt++) {
        int r0 = wy * 64 + mt * 16 + (lane >> 2);
#pragma unroll
        for (int nt = 0; nt < 4; nt++) {
            int cl = wx * 32 + nt * 8 + (lane & 3) * 2;
            float b0 = bias[n0 + cl], b1 = bias[n0 + cl + 1];
            *(float2*)&sC[r0 * CPITCH + cl] =
                make_float2(acc[mt][nt][0] + b0, acc[mt][nt][1] + b1);
            *(float2*)&sC[(r0 + 8) * CPITCH + cl] =
                make_float2(acc[mt][nt][2] + b0, acc[mt][nt][3] + b1);
        }
    }
    __syncthreads();

    const float SCALE = 0.08838834764831845f;
    for (int e = tid; e < 8192; e += 512) {
        int i  = e & 31;
        int hl = (e >> 5) & 1;
        int r  = e >> 6;
        int d0 = 2 * i;
        int row = m0 + r;
        int bb = row >> 10, s = row & 1023;

        float2 vlo = *(float2*)&sC[r * CPITCH + hl * 128 + d0];
        float2 vhi = *(float2*)&sC[r * CPITCH + hl * 128 + 64 + d0];
        int cg = n0 + hl * 128;

        float2 c_lo = *(const float2*)&cosp[s * D_ + d0];
        float2 c_hi = *(const float2*)&cosp[s * D_ + 64 + d0];
        float2 s_lo = *(const float2*)&sinp[s * D_ + d0];
        float2 s_hi = *(const float2*)&sinp[s * D_ + 64 + d0];

        if (cg < NH_ * D_) {
            int h = cg >> 7;
            float o0 = (vlo.x * c_lo.x - vhi.x * s_lo.x) * SCALE;
            float o1 = (vlo.y * c_lo.y - vhi.y * s_lo.y) * SCALE;
            float o2 = (vhi.x * c_hi.x + vlo.x * s_hi.x) * SCALE;
            float o3 = (vhi.y * c_hi.y + vlo.y * s_hi.y) * SCALE;
            size_t base = (((size_t)bb * NH_ + h) * S_ + s) * D_;
            uint32_t hw, lw;
            pack_hilo_h(o0, o1, hw, lw);
            *(uint32_t*)(g_qh + base + d0) = hw;
            *(uint32_t*)(g_ql + base + d0) = lw;
            pack_hilo_h(o2, o3, hw, lw);
            *(uint32_t*)(g_qh + base + 64 + d0) = hw;
            *(uint32_t*)(g_ql + base + 64 + d0) = lw;
        } else {
            int kvh = (cg - NH_ * D_) >> 7;
            float o0 = vlo.x * c_lo.x - vhi.x * s_lo.x;
            float o1 = vlo.y * c_lo.y - vhi.y * s_lo.y;
            float o2 = vhi.x * c_hi.x + vlo.x * s_hi.x;
            float o3 = vhi.y * c_hi.y + vlo.y * s_hi.y;
            size_t base = (((size_t)bb * NKV_ + kvh) * S_ + s) * D_;
            uint32_t hw, lw;
            pack_hilo_h(o0, o1, hw, lw);
            *(uint32_t*)(g_kh + base + d0) = hw;
            *(uint32_t*)(g_kl + base + d0) = lw;
            pack_hilo_h(o2, o3, hw, lw);
            *(uint32_t*)(g_kh + base + 64 + d0) = hw;
            *(uint32_t*)(g_kl + base + 64 + d0) = lw;
        }
    }
}

/* ============== GEMM2: single-product fp16, f32 accum ===================== */
#define H1_SA 0
#define H1_SB (128 * 40)
#define H1_STAGE_E (384 * 40)
#define H1_STAGE_B (H1_STAGE_E * 2)
#define H1_STAGES 4
#define H1_SMEM (H1_STAGES * H1_STAGE_B)    /* 122880 B */

__global__ void __launch_bounds__(512, 1) gemm_h1(
    const __half* __restrict__ Ah, const __half* __restrict__ Bh,
    const float* __restrict__ bias, float* __restrict__ C, int N, int K)
{
    extern __shared__ __half hsmem[];
    const uint32_t sb = smem_u32(hsmem);

    const int tid  = threadIdx.x;
    const int lane = tid & 31;
    const int wid  = tid >> 5;
    const int wy   = wid >> 3;
    const int wx   = wid & 7;
    const int m0   = blockIdx.y * 128;
    const int n0   = blockIdx.x * 256;
    const int KT   = K / 32;

    const int lr = tid >> 2;
    const int lc = (tid & 3) * 8;
    const uint32_t doff = (uint32_t)(lr * 40 + lc) * 2;

    float acc[4][4][4];
#pragma unroll
    for (int mt = 0; mt < 4; mt++)
#pragma unroll
        for (int nt = 0; nt < 4; nt++)
#pragma unroll
            for (int j = 0; j < 4; j++) acc[mt][nt][j] = 0.f;

    const int a_row = wy * 64 + (lane & 15);
    const int a_col = (lane >> 4) * 8;
    const uint32_t a_off = (uint32_t)(a_row * 40 + a_col) * 2;
    const int b_row = wx * 32 + ((lane >> 4) << 3) + (lane & 7);
    const int b_col = ((lane >> 3) & 1) * 8;
    const uint32_t b_off = (uint32_t)(b_row * 40 + b_col) * 2;

#define H1_LOAD(kt, st) do {                                              \
        const int k0_ = (kt) * 32;                                        \
        const uint32_t s0_ = sb + (st) * H1_STAGE_B + doff;               \
        size_t asrc_ = (size_t)(m0 + lr) * K + k0_ + lc;                  \
        cp_async16(s0_ + H1_SA * 2, Ah + asrc_);                          \
        _Pragma("unroll")                                                 \
        for (int p_ = 0; p_ < 2; p_++) {                                  \
            size_t bsrc_ = (size_t)(n0 + p_ * 128 + lr) * K + k0_ + lc;   \
            cp_async16(s0_ + (H1_SB + p_ * 128 * 40) * 2, Bh + bsrc_);    \
        }                                                                 \
    } while (0)

    H1_LOAD(0, 0); CP_COMMIT();
    H1_LOAD(1, 1); CP_COMMIT();
    H1_LOAD(2, 2); CP_COMMIT();

    int st = 0;
    for (int kt = 0; kt < KT; kt++) {
        if (kt + 2 < KT)      { CP_WAIT(2); }
        else if (kt + 1 < KT) { CP_WAIT(1); }
        else                  { CP_WAIT(0); }
        __syncthreads();
        if (kt + 3 < KT) {
            int st3 = st + 3; if (st3 >= H1_STAGES) st3 -= H1_STAGES;
            H1_LOAD(kt + 3, st3);
            CP_COMMIT();
        }

        const uint32_t stb = sb + st * H1_STAGE_B;
#pragma unroll
        for (int ks = 0; ks < 32; ks += 16) {
            const uint32_t kso = (uint32_t)ks * 2;
            uint32_t bh[4][2];
#pragma unroll
            for (int nt2 = 0; nt2 < 2; nt2++) {
                uint32_t bo = stb + (H1_SB * 2) + b_off +
                              (uint32_t)(nt2 * 16 * 40) * 2 + kso;
                uint32_t r[4];
                ldsm4(r, bo);
                bh[nt2 * 2][0] = r[0]; bh[nt2 * 2][1] = r[1];
                bh[nt2 * 2 + 1][0] = r[2]; bh[nt2 * 2 + 1][1] = r[3];
            }
#pragma unroll
            for (int mt = 0; mt < 4; mt++) {
                uint32_t ah[4];
                uint32_t ao = stb + a_off + (uint32_t)(mt * 16 * 40) * 2 + kso;
                ldsm4(ah, ao);
#pragma unroll
                for (int nt = 0; nt < 4; nt++)
                    mma_h_f32(acc[mt][nt], ah, bh[nt]);
            }
        }
        st++; if (st >= H1_STAGES) st -= H1_STAGES;
    }
#undef H1_LOAD

#pragma unroll
    for (int mt = 0; mt < 4; mt++) {
        int row0 = m0 + wy * 64 + mt * 16 + (lane >> 2);
#pragma unroll
        for (int nt = 0; nt < 4; nt++) {
            int col = n0 + wx * 32 + nt * 8 + (lane & 3) * 2;
            float b0 = bias[col], b1 = bias[col + 1];
            float2 v0 = {acc[mt][nt][0] + b0, acc[mt][nt][1] + b1};
            float2 v1 = {acc[mt][nt][2] + b0, acc[mt][nt][3] + b1};
            *(float2*)(C + (size_t)row0 * N + col)       = v0;
            *(float2*)(C + (size_t)(row0 + 8) * N + col) = v1;
        }
    }
}

/* ============ HMMA flash attention: QK fp16x3, PV fp16x1 ================== */
#define AT_PAD 136
#define AQ_L   (128 * AT_PAD)
#define AST0   (2 * 128 * AT_PAD)
#define AMAT   (64 * AT_PAD)
#define ASTAGE (3 * AMAT)
#define ATTN_SMEM_B ((AST0 + 2 * ASTAGE) * 2)   /* 174080 B */
#define LOG2E 1.4426950408889634f

__global__ void __launch_bounds__(256, 1) attn_mma()
{
    const int qbx = blockIdx.x, h = blockIdx.y, b = blockIdx.z;
    const int kvh = h >> 2;
    const int qlo = qbx * 128;

    extern __shared__ __half asmem[];
    const uint32_t sb = smem_u32(asmem);
    const int tid = threadIdx.x, lane = tid & 31, w = tid >> 5;

    const __half* Qhg = g_qh + (((size_t)b * NH_ + h) * S_ + qlo) * D_;
    const __half* Qlg = g_ql + (((size_t)b * NH_ + h) * S_ + qlo) * D_;
    const __half* Khg = g_kh + ((size_t)b * NKV_ + kvh) * S_ * D_;
    const __half* Klg = g_kl + ((size_t)b * NKV_ + kvh) * S_ * D_;
    const __half* Vg  = g_v  + ((size_t)b * NKV_ + kvh) * S_ * D_;

    for (int c = tid; c < 2048; c += 256) {
        int row = c >> 4, ch = c & 15;
        uint32_t dq = sb + (uint32_t)(row * AT_PAD + ch * 8) * 2;
        size_t src = (size_t)row * D_ + ch * 8;
        cp_async16(dq, Qhg + src);
        cp_async16(dq + AQ_L * 2, Qlg + src);
    }

#define LOAD_KV(kb, st) do {                                            \
        const int kbase_ = (kb) * 64;                                   \
        const uint32_t s0_ = sb + (uint32_t)(AST0 + (st) * ASTAGE) * 2; \
        for (int c = tid; c < 1024; c += 256) {                         \
            int row_ = c >> 4, ch_ = c & 15;                            \
            uint32_t d_ = s0_ + (uint32_t)(row_ * AT_PAD + ch_ * 8) * 2;\
            size_t src_ = (size_t)(kbase_ + row_) * D_ + ch_ * 8;       \
            cp_async16(d_,                Khg + src_);                  \
            cp_async16(d_ + AMAT * 2,     Klg + src_);                  \
            cp_async16(d_ + 2 * AMAT * 2, Vg  + src_);                  \
        } } while (0)

    int kstart = qlo - (WINDOW_ - 1);
    if (kstart < 0) kstart = 0;
    const int kb0 = kstart >> 6;
    const int kb1 = (qlo + 127) >> 6;

    LOAD_KV(kb0, 0);
    CP_COMMIT();

    float oacc[16][4];
#pragma unroll
    for (int nf = 0; nf < 16; nf++)
#pragma unroll
        for (int j = 0; j < 4; j++) oacc[nf][j] = 0.f;
    float m0 = -1e30f, m1 = -1e30f, l0 = 0.f, l1 = 0.f;

    const int qg0 = qlo + w * 16 + (lane >> 2);
    const int qg1 = qg0 + 8;
    const uint32_t qrow_off =
        (uint32_t)((w * 16 + (lane & 15)) * AT_PAD + (lane >> 4) * 8) * 2;
    const uint32_t krow_off =
        (uint32_t)((((lane >> 4) << 3) + (lane & 7)) * AT_PAD +
                   ((lane >> 3) & 1) * 8) * 2;
    const uint32_t vrow_off =
        (uint32_t)((lane & 15) * AT_PAD + (lane >> 4) * 8) * 2;

    for (int kb = kb0; kb <= kb1; kb++) {
        const int st = (kb - kb0) & 1;
        if (kb < kb1) {
            LOAD_KV(kb + 1, st ^ 1);
            CP_COMMIT();
            CP_WAIT(1);
        } else {
            CP_WAIT(0);
        }
        __syncthreads();

        const uint32_t stb = sb + (uint32_t)(AST0 + st * ASTAGE) * 2;
        const int kbase = kb * 64;

        float sacc[8][4];
#pragma unroll
        for (int j = 0; j < 8; j++)
#pragma unroll
            for (int i = 0; i < 4; i++) sacc[j][i] = 0.f;

#pragma unroll
        for (int kk = 0; kk < 8; kk++) {
            uint32_t qh[4], ql[4];
            const uint32_t qoff = sb + qrow_off + kk * 32;
            ldsm4(qh, qoff);
            ldsm4(ql, qoff + AQ_L * 2);
#pragma unroll
            for (int nb = 0; nb < 4; nb++) {
                uint32_t kh[4], kl[4];
                const uint32_t koff = stb + krow_off +
                    (uint32_t)(nb * 16 * AT_PAD) * 2 + kk * 32;
                ldsm4(kh, koff);
                ldsm4(kl, koff + AMAT * 2);
                mma_h_f32(sacc[2 * nb],     qh, kh);
                mma_h_f32(sacc[2 * nb],     qh, kl);
                mma_h_f32(sacc[2 * nb],     ql, kh);
                mma_h_f32(sacc[2 * nb + 1], qh, &kh[2]);
                mma_h_f32(sacc[2 * nb + 1], qh, &kl[2]);
                mma_h_f32(sacc[2 * nb + 1], ql, &kh[2]);
            }
        }

#pragma unroll
        for (int j = 0; j < 8; j++) {
            const int kg0 = kbase + 8 * j + 2 * (lane & 3);
            const int kg1 = kg0 + 1;
            if (!(kg0 <= qg0 && qg0 - kg0 < WINDOW_)) sacc[j][0] = -1e30f;
            if (!(kg1 <= qg0 && qg0 - kg1 < WINDOW_)) sacc[j][1] = -1e30f;
            if (!(kg0 <= qg1 && qg1 - kg0 < WINDOW_)) sacc[j][2] = -1e30f;
            if (!(kg1 <= qg1 && qg1 - kg1 < WINDOW_)) sacc[j][3] = -1e30f;
        }

        float mx0 = m0, mx1 = m1;
#pragma unroll
        for (int j = 0; j < 8; j++) {
            mx0 = fmaxf(mx0, fmaxf(sacc[j][0], sacc[j][1]));
            mx1 = fmaxf(mx1, fmaxf(sacc[j][2], sacc[j][3]));
        }
        mx0 = fmaxf(mx0, __shfl_xor_sync(0xffffffffu, mx0, 1));
        mx0 = fmaxf(mx0, __shfl_xor_sync(0xffffffffu, mx0, 2));
        mx1 = fmaxf(mx1, __shfl_xor_sync(0xffffffffu, mx1, 1));
        mx1 = fmaxf(mx1, __shfl_xor_sync(0xffffffffu, mx1, 2));

        const float sc0 = ex2f((m0 - mx0) * LOG2E);
        const float sc1 = ex2f((m1 - mx1) * LOG2E);
        float la0 = 0.f, la1 = 0.f;
#pragma unroll
        for (int j = 0; j < 8; j++) {
            float p0 = (sacc[j][0] > -1e29f) ? ex2f((sacc[j][0] - mx0) * LOG2E) : 0.f;
            float p1 = (sacc[j][1] > -1e29f) ? ex2f((sacc[j][1] - mx0) * LOG2E) : 0.f;
            float p2 = (sacc[j][2] > -1e29f) ? ex2f((sacc[j][2] - mx1) * LOG2E) : 0.f;
            float p3 = (sacc[j][3] > -1e29f) ? ex2f((sacc[j][3] - mx1) * LOG2E) : 0.f;
            sacc[j][0] = p0; sacc[j][1] = p1; sacc[j][2] = p2; sacc[j][3] = p3;
            la0 += p0 + p1;
            la1 += p2 + p3;
        }
        la0 += __shfl_xor_sync(0xffffffffu, la0, 1);
        la0 += __shfl_xor_sync(0xffffffffu, la0, 2);
        la1 += __shfl_xor_sync(0xffffffffu, la1, 1);
        la1 += __shfl_xor_sync(0xffffffffu, la1, 2);
        l0 = l0 * sc0 + la0;
        l1 = l1 * sc1 + la1;
        m0 = mx0; m1 = mx1;

#pragma unroll
        for (int nf = 0; nf < 16; nf++) {
            oacc[nf][0] *= sc0; oacc[nf][1] *= sc0;
            oacc[nf][2] *= sc1; oacc[nf][3] *= sc1;
        }

#pragma unroll
        for (int s4 = 0; s4 < 4; s4++) {
            uint32_t ah[4];
            ah[0] = pack_h(sacc[2 * s4][0],     sacc[2 * s4][1]);
            ah[1] = pack_h(sacc[2 * s4][2],     sacc[2 * s4][3]);
            ah[2] = pack_h(sacc[2 * s4 + 1][0], sacc[2 * s4 + 1][1]);
            ah[3] = pack_h(sacc[2 * s4 + 1][2], sacc[2 * s4 + 1][3]);

            const uint32_t vbase = stb + 2 * AMAT * 2 + vrow_off +
                                   (uint32_t)(s4 * 16 * AT_PAD) * 2;
#pragma unroll
            for (int db = 0; db < 8; db++) {
                uint32_t vh[4];
                ldsm4t(vh, vbase + db * 32);
                mma_h_f32(oacc[2 * db],     ah, vh);
                mma_h_f32(oacc[2 * db + 1], ah, &vh[2]);
            }
        }
        __syncthreads();
    }
#undef LOAD_KV

    const float inv0 = 1.f / l0;
    const float inv1 = 1.f / l1;
    const size_t o0 = (size_t)(b * S_ + qg0) * (NH_ * D_) + h * D_;
    const size_t o1 = (size_t)(b * S_ + qg1) * (NH_ * D_) + h * D_;
#pragma unroll
    for (int nf = 0; nf < 16; nf++) {
        const int dc = 8 * nf + 2 * (lane & 3);
        *(uint32_t*)(g_at_h + o0 + dc) =
            pack_h(oacc[nf][0] * inv0, oacc[nf][1] * inv0);
        *(uint32_t*)(g_at_h + o1 + dc) =
            pack_h(oacc[nf][2] * inv1, oacc[nf][3] * inv1);
    }
}

/* --------------------------------- launch --------------------------------- */
extern "C" void kernel_launch(void* const* d_in, const int* in_sizes, int n_in,
                              void* d_out, int out_size)
{
    const float* hidden = (const float*)d_in[0];
    const float* cosp   = (const float*)d_in[1];
    const float* sinp   = (const float*)d_in[2];
    const float* w_qkv  = (const float*)d_in[3];
    const float* b_qkv  = (const float*)d_in[4];
    const float* w_o    = (const float*)d_in[5];
    const float* b_o    = (const float*)d_in[6];
    float* out = (float*)d_out;

    __half *p_h_hi, *p_h_lo, *p_wq_hi, *p_wq_lo, *p_wo_h, *p_at_h;
    cudaGetSymbolAddress((void**)&p_h_hi, g_h_hi);
    cudaGetSymbolAddress((void**)&p_h_lo, g_h_lo);
    cudaGetSymbolAddress((void**)&p_wq_hi, g_wq_hi);
    cudaGetSymbolAddress((void**)&p_wq_lo, g_wq_lo);
    cudaGetSymbolAddress((void**)&p_wo_h, g_wo_h);
    cudaGetSymbolAddress((void**)&p_at_h, g_at_h);

    cudaFuncSetAttribute(gemm1_u,
                         cudaFuncAttributeMaxDynamicSharedMemorySize, GSMEM);
    cudaFuncSetAttribute(gemm_h1,
                         cudaFuncAttributeMaxDynamicSharedMemorySize, H1_SMEM);
    cudaFuncSetAttribute(attn_mma,
                         cudaFuncAttributeMaxDynamicSharedMemorySize, ATTN_SMEM_B);

    /* converts */
    cvt_split_h<<<(BS_ * HID_ / 4 + 255) / 256, 256>>>(hidden, p_h_hi, p_h_lo,
                                                       BS_ * HID_ / 4);
    cvt_split_h<<<(QKV_OUT_ * HID_ / 4 + 255) / 256, 256>>>(w_qkv, p_wq_hi,
                                                            p_wq_lo,
                                                            QKV_OUT_ * HID_ / 4);
    cvt_h<<<(HID_ * HID_ / 4 + 255) / 256, 256>>>(w_o, p_wo_h,
                                                  HID_ * HID_ / 4);

    /* 1) dual-path qkv GEMM (QK fp16x3 + RoPE; V fp16x1), one launch */
    gemm1_u<<<dim3(QKV_OUT_ / 256, BS_ / 128), 512, GSMEM>>>(
        p_h_hi, p_h_lo, p_wq_hi, p_wq_lo, b_qkv, cosp, sinp, HID_);

    /* 2) flash attention (QK fp16x3, PV fp16x1) */
    attn_mma<<<dim3(S_ / 128, NH_, B_), 256, ATTN_SMEM_B>>>();

    /* 3) out = attn @ w_o^T + b_o (single-product fp16) */
    gemm_h1<<<dim3(HID_ / 256, BS_ / 128), 512, H1_SMEM>>>(
        p_at_h, p_wo_h, b_o, out, HID_, HID_);
}

// round 16
// speedup vs baseline: 2.1857x; 1.0090x over previous
#include <cuda_runtime.h>
#include <cuda_fp16.h>
#include <cstdint>
#include <math.h>

#define B_ 2
#define S_ 1024
#define HID_ 4096
#define NH_ 32
#define NKV_ 8
#define D_ 128
#define WINDOW_ 512
#define QKV_OUT_ ((NH_ + 2 * NKV_) * D_)   /* 6144 */
#define BS_ (B_ * S_)                      /* 2048 */
#define VSTART_ ((NH_ + NKV_) * D_)        /* 5120 */

/* ------------------------- scratch (static device globals) ---------------- */
__device__ __half g_qh[B_ * NH_ * S_ * D_];
__device__ __half g_ql[B_ * NH_ * S_ * D_];
__device__ __half g_kh[B_ * NKV_ * S_ * D_];
__device__ __half g_kl[B_ * NKV_ * S_ * D_];
__device__ __half g_v [B_ * NKV_ * S_ * D_];

__device__ __half g_h_hi[BS_ * HID_];
__device__ __half g_h_lo[BS_ * HID_];
__device__ __half g_wq_hi[QKV_OUT_ * HID_];
__device__ __half g_wq_lo[QKV_OUT_ * HID_];
__device__ __half g_wo_h[HID_ * HID_];
__device__ __half g_at_h[BS_ * HID_];

/* ============================ PTX helpers (base ISA only) ================= */
__device__ __forceinline__ uint32_t smem_u32(const void* p) {
    return (uint32_t)__cvta_generic_to_shared(p);
}
__device__ __forceinline__ void cp_async16(uint32_t dst, const void* src) {
    asm volatile("cp.async.cg.shared.global [%0], [%1], 16;\n"
                 :: "r"(dst), "l"(src));
}
#define CP_COMMIT() asm volatile("cp.async.commit_group;\n" ::: "memory")
#define CP_WAIT(n)  asm volatile("cp.async.wait_group %0;\n" :: "n"(n) : "memory")

__device__ __forceinline__ void ldsm4(uint32_t* r, uint32_t addr) {
    asm volatile("ldmatrix.sync.aligned.m8n8.x4.shared.b16 {%0,%1,%2,%3}, [%4];"
                 : "=r"(r[0]), "=r"(r[1]), "=r"(r[2]), "=r"(r[3]) : "r"(addr));
}
__device__ __forceinline__ void ldsm4t(uint32_t* r, uint32_t addr) {
    asm volatile("ldmatrix.sync.aligned.m8n8.x4.trans.shared.b16 {%0,%1,%2,%3}, [%4];"
                 : "=r"(r[0]), "=r"(r[1]), "=r"(r[2]), "=r"(r[3]) : "r"(addr));
}
__device__ __forceinline__ void mma_h_f32(float* d, const uint32_t* a,
                                          const uint32_t* b) {
    asm volatile("mma.sync.aligned.m16n8k16.row.col.f32.f16.f16.f32 "
                 "{%0,%1,%2,%3}, {%4,%5,%6,%7}, {%8,%9}, {%0,%1,%2,%3};"
                 : "+f"(d[0]), "+f"(d[1]), "+f"(d[2]), "+f"(d[3])
                 : "r"(a[0]), "r"(a[1]), "r"(a[2]), "r"(a[3]),
                   "r"(b[0]), "r"(b[1]));
}
__device__ __forceinline__ float ex2f(float x) {
    float y;
    asm("ex2.approx.f32 %0, %1;" : "=f"(y) : "f"(x));
    return y;
}
__device__ __forceinline__ void pack_hilo_h(float x, float y,
                                            uint32_t& hw, uint32_t& lw) {
    __half2 h = __floats2half2_rn(x, y);
    float2 hf = __half22float2(h);
    __half2 l = __floats2half2_rn(x - hf.x, y - hf.y);
    hw = *(uint32_t*)&h;
    lw = *(uint32_t*)&l;
}
__device__ __forceinline__ uint32_t pack_h(float x, float y) {
    __half2 h = __floats2half2_rn(x, y);
    return *(uint32_t*)&h;
}

/* ==================== fp32 -> fp16 hi/lo split ============================ */
__global__ void cvt_split_h(const float* __restrict__ x,
                            __half* __restrict__ hi,
                            __half* __restrict__ lo, int n4)
{
    int i = blockIdx.x * blockDim.x + threadIdx.x;
    if (i >= n4) return;
    float4 v = ((const float4*)x)[i];
    uint2 hw, lw;
    uint32_t a, b;
    pack_hilo_h(v.x, v.y, a, b); hw.x = a; lw.x = b;
    pack_hilo_h(v.z, v.w, a, b); hw.y = a; lw.y = b;
    ((uint2*)hi)[i] = hw;
    ((uint2*)lo)[i] = lw;
}

/* ==================== fp32 -> fp16 (hi only) ============================== */
__global__ void cvt_h(const float* __restrict__ x,
                      __half* __restrict__ hi, int n4)
{
    int i = blockIdx.x * blockDim.x + threadIdx.x;
    if (i >= n4) return;
    float4 v = ((const float4*)x)[i];
    uint2 hw;
    hw.x = pack_h(v.x, v.y);
    hw.y = pack_h(v.z, v.w);
    ((uint2*)hi)[i] = hw;
}

/* ====== GEMM1: 128x128 tiles, dual-path (QK fp16x3+RoPE | V fp16x1) ====== */
/* 768 CTAs of 256 threads (8 warps, 2x4 of 64x32 warp tiles), BK=32,
   3-stage ring. Fine tiles -> better SM work balance (no 3-heavy SMs).    */
#define G1_SA_HI 0
#define G1_SA_LO (128 * 40)
#define G1_SB_HI (2 * 128 * 40)
#define G1_SB_LO (3 * 128 * 40)
#define G1_STAGE_E (4 * 128 * 40)          /* 20480 halves */
#define G1_STAGE_B (G1_STAGE_E * 2)        /* 40960 B      */
#define G1_STAGES 3
#define G1_SMEM (G1_STAGES * G1_STAGE_B)   /* 122880 B     */
#define G1_CP 132

__global__ void __launch_bounds__(256, 1) gemm1_u(
    const __half* __restrict__ Ah, const __half* __restrict__ Al,
    const __half* __restrict__ Bh, const __half* __restrict__ Bl,
    const float* __restrict__ bias,
    const float* __restrict__ cosp, const float* __restrict__ sinp,
    int K)
{
    extern __shared__ __half smem[];
    const uint32_t sb = smem_u32(smem);

    const int tid  = threadIdx.x;
    const int lane = tid & 31;
    const int wid  = tid >> 5;
    const int wy   = wid >> 2;          /* 0..1 : 64-row band */
    const int wx   = wid & 3;           /* 0..3 : 32-col band */
    const int m0   = blockIdx.y * 128;
    const int n0   = blockIdx.x * 128;
    const int KT   = K / 32;

    /* loader: 256 threads, each handles rows lr and lr+64, one 16B chunk */
    const int lr = tid >> 2;            /* 0..63 */
    const int lc = (tid & 3) * 8;       /* 0,8,16,24 halves */
    const uint32_t doff = (uint32_t)(lr * 40 + lc) * 2;
#define ROW2 (64 * 40 * 2)

    const uint32_t a_off = (uint32_t)((wy * 64 + (lane & 15)) * 40 +
                                      (lane >> 4) * 8) * 2;
    const uint32_t b_off = (uint32_t)((wx * 32 + ((lane >> 4) << 3) +
                                       (lane & 7)) * 40 +
                                      ((lane >> 3) & 1) * 8) * 2;

    float acc[4][4][4];
#pragma unroll
    for (int mt = 0; mt < 4; mt++)
#pragma unroll
        for (int nt = 0; nt < 4; nt++)
#pragma unroll
            for (int j = 0; j < 4; j++) acc[mt][nt][j] = 0.f;

    if (n0 >= VSTART_) {
        /* ---------------- V path: single product ------------------------ */
#define V_LOAD(kt, st) do {                                                \
        const int k0_ = (kt) * 32;                                         \
        const uint32_t s0_ = sb + (st) * G1_STAGE_B + doff;                \
        size_t a0_ = (size_t)(m0 + lr) * K + k0_ + lc;                     \
        size_t a1_ = (size_t)(m0 + 64 + lr) * K + k0_ + lc;                \
        size_t b0_ = (size_t)(n0 + lr) * K + k0_ + lc;                     \
        size_t b1_ = (size_t)(n0 + 64 + lr) * K + k0_ + lc;                \
        cp_async16(s0_ + G1_SA_HI * 2,        Ah + a0_);                   \
        cp_async16(s0_ + G1_SA_HI * 2 + ROW2, Ah + a1_);                   \
        cp_async16(s0_ + G1_SB_HI * 2,        Bh + b0_);                   \
        cp_async16(s0_ + G1_SB_HI * 2 + ROW2, Bh + b1_);                   \
    } while (0)

        V_LOAD(0, 0); CP_COMMIT();
        V_LOAD(1, 1); CP_COMMIT();

        int st = 0;
        for (int kt = 0; kt < KT; kt++) {
            if (kt + 1 < KT) { CP_WAIT(1); } else { CP_WAIT(0); }
            __syncthreads();
            if (kt + 2 < KT) {
                int st2 = st + 2; if (st2 >= G1_STAGES) st2 -= G1_STAGES;
                V_LOAD(kt + 2, st2);
                CP_COMMIT();
            }

            const uint32_t stb = sb + st * G1_STAGE_B;
#pragma unroll
            for (int ks = 0; ks < 32; ks += 16) {
                const uint32_t kso = (uint32_t)ks * 2;
                uint32_t bh[4][2];
#pragma unroll
                for (int nt2 = 0; nt2 < 2; nt2++) {
                    uint32_t bo = stb + b_off +
                                  (uint32_t)(nt2 * 16 * 40) * 2 + kso;
                    uint32_t r[4];
                    ldsm4(r, bo + G1_SB_HI * 2);
                    bh[nt2 * 2][0] = r[0]; bh[nt2 * 2][1] = r[1];
                    bh[nt2 * 2 + 1][0] = r[2]; bh[nt2 * 2 + 1][1] = r[3];
                }
#pragma unroll
                for (int mt = 0; mt < 4; mt++) {
                    uint32_t ah[4];
                    uint32_t ao = stb + a_off +
                                  (uint32_t)(mt * 16 * 40) * 2 + kso;
                    ldsm4(ah, ao + G1_SA_HI * 2);
#pragma unroll
                    for (int nt = 0; nt < 4; nt++)
                        mma_h_f32(acc[mt][nt], ah, bh[nt]);
                }
            }
            st++; if (st >= G1_STAGES) st -= G1_STAGES;
        }
#undef V_LOAD

        const int kvh = (n0 - VSTART_) >> 7;
#pragma unroll
        for (int mt = 0; mt < 4; mt++) {
            int row0 = m0 + wy * 64 + mt * 16 + (lane >> 2);
            int bb0 = row0 >> 10, s0r = row0 & 1023;
            int row1 = row0 + 8;
            int bb1 = row1 >> 10, s1r = row1 & 1023;
#pragma unroll
            for (int nt = 0; nt < 4; nt++) {
                int col = n0 + wx * 32 + nt * 8 + (lane & 3) * 2;
                int d0 = col & 127;
                float b0 = bias[col], b1 = bias[col + 1];
                size_t base0 = (((size_t)bb0 * NKV_ + kvh) * S_ + s0r) * D_ + d0;
                size_t base1 = (((size_t)bb1 * NKV_ + kvh) * S_ + s1r) * D_ + d0;
                *(uint32_t*)(g_v + base0) =
                    pack_h(acc[mt][nt][0] + b0, acc[mt][nt][1] + b1);
                *(uint32_t*)(g_v + base1) =
                    pack_h(acc[mt][nt][2] + b0, acc[mt][nt][3] + b1);
            }
        }
        return;
    }

    /* ---------------- QK path: 3-product + fused RoPE -------------------- */
#define QK_LOAD(kt, st) do {                                               \
        const int k0_ = (kt) * 32;                                         \
        const uint32_t s0_ = sb + (st) * G1_STAGE_B + doff;                \
        size_t a0_ = (size_t)(m0 + lr) * K + k0_ + lc;                     \
        size_t a1_ = (size_t)(m0 + 64 + lr) * K + k0_ + lc;                \
        size_t b0_ = (size_t)(n0 + lr) * K + k0_ + lc;                     \
        size_t b1_ = (size_t)(n0 + 64 + lr) * K + k0_ + lc;                \
        cp_async16(s0_ + G1_SA_HI * 2,        Ah + a0_);                   \
        cp_async16(s0_ + G1_SA_HI * 2 + ROW2, Ah + a1_);                   \
        cp_async16(s0_ + G1_SA_LO * 2,        Al + a0_);                   \
        cp_async16(s0_ + G1_SA_LO * 2 + ROW2, Al + a1_);                   \
        cp_async16(s0_ + G1_SB_HI * 2,        Bh + b0_);                   \
        cp_async16(s0_ + G1_SB_HI * 2 + ROW2, Bh + b1_);                   \
        cp_async16(s0_ + G1_SB_LO * 2,        Bl + b0_);                   \
        cp_async16(s0_ + G1_SB_LO * 2 + ROW2, Bl + b1_);                   \
    } while (0)

    QK_LOAD(0, 0); CP_COMMIT();
    QK_LOAD(1, 1); CP_COMMIT();

    int st = 0;
    for (int kt = 0; kt < KT; kt++) {
        if (kt + 1 < KT) { CP_WAIT(1); } else { CP_WAIT(0); }
        __syncthreads();
        if (kt + 2 < KT) {
            int st2 = st + 2; if (st2 >= G1_STAGES) st2 -= G1_STAGES;
            QK_LOAD(kt + 2, st2);
            CP_COMMIT();
        }

        const uint32_t stb = sb + st * G1_STAGE_B;
#pragma unroll
        for (int ks = 0; ks < 32; ks += 16) {
            const uint32_t kso = (uint32_t)ks * 2;
            uint32_t bh[4][2], bl[4][2];
#pragma unroll
            for (int nt2 = 0; nt2 < 2; nt2++) {
                uint32_t bo = stb + b_off + (uint32_t)(nt2 * 16 * 40) * 2 + kso;
                uint32_t r[4];
                ldsm4(r, bo + G1_SB_HI * 2);
                bh[nt2 * 2][0] = r[0]; bh[nt2 * 2][1] = r[1];
                bh[nt2 * 2 + 1][0] = r[2]; bh[nt2 * 2 + 1][1] = r[3];
                ldsm4(r, bo + G1_SB_LO * 2);
                bl[nt2 * 2][0] = r[0]; bl[nt2 * 2][1] = r[1];
                bl[nt2 * 2 + 1][0] = r[2]; bl[nt2 * 2 + 1][1] = r[3];
            }
#pragma unroll
            for (int mt = 0; mt < 4; mt++) {
                uint32_t ah[4], al[4];
                uint32_t ao = stb + a_off + (uint32_t)(mt * 16 * 40) * 2 + kso;
                ldsm4(ah, ao + G1_SA_HI * 2);
                ldsm4(al, ao + G1_SA_LO * 2);
#pragma unroll
                for (int nt = 0; nt < 4; nt++)
                    mma_h_f32(acc[mt][nt], ah, bh[nt]);
#pragma unroll
                for (int nt = 0; nt < 4; nt++)
                    mma_h_f32(acc[mt][nt], ah, bl[nt]);
#pragma unroll
                for (int nt = 0; nt < 4; nt++)
                    mma_h_f32(acc[mt][nt], al, bh[nt]);
            }
        }
        st++; if (st >= G1_STAGES) st -= G1_STAGES;
    }
#undef QK_LOAD

    /* epilogue: stage fp32 to smem; band = exactly ONE head */
    __syncthreads();
    float* sC = (float*)smem;
#pragma unroll
    for (int mt = 0; mt < 4; mt++) {
        int r0 = wy * 64 + mt * 16 + (lane >> 2);
#pragma unroll
        for (int nt = 0; nt < 4; nt++) {
            int cl = wx * 32 + nt * 8 + (lane & 3) * 2;
            float b0 = bias[n0 + cl], b1 = bias[n0 + cl + 1];
            *(float2*)&sC[r0 * G1_CP + cl] =
                make_float2(acc[mt][nt][0] + b0, acc[mt][nt][1] + b1);
            *(float2*)&sC[(r0 + 8) * G1_CP + cl] =
                make_float2(acc[mt][nt][2] + b0, acc[mt][nt][3] + b1);
        }
    }
    __syncthreads();

    const float SCALE = 0.08838834764831845f;
    const bool isQ = (n0 < NH_ * D_);
    const int head = isQ ? (n0 >> 7) : ((n0 - NH_ * D_) >> 7);
    __half* outh = isQ ? g_qh : g_kh;
    __half* outl = isQ ? g_ql : g_kl;
    const int nheads = isQ ? NH_ : NKV_;
    const float qsc = isQ ? SCALE : 1.f;

    for (int e = tid; e < 4096; e += 256) {
        int i = e & 31;
        int r = e >> 5;
        int d0 = 2 * i;
        int row = m0 + r;
        int bb = row >> 10, s = row & 1023;

        float2 vlo = *(float2*)&sC[r * G1_CP + d0];
        float2 vhi = *(float2*)&sC[r * G1_CP + 64 + d0];
        float2 c_lo = *(const float2*)&cosp[s * D_ + d0];
        float2 c_hi = *(const float2*)&cosp[s * D_ + 64 + d0];
        float2 s_lo = *(const float2*)&sinp[s * D_ + d0];
        float2 s_hi = *(const float2*)&sinp[s * D_ + 64 + d0];

        float o0 = (vlo.x * c_lo.x - vhi.x * s_lo.x) * qsc;
        float o1 = (vlo.y * c_lo.y - vhi.y * s_lo.y) * qsc;
        float o2 = (vhi.x * c_hi.x + vlo.x * s_hi.x) * qsc;
        float o3 = (vhi.y * c_hi.y + vlo.y * s_hi.y) * qsc;
        size_t base = (((size_t)bb * nheads + head) * S_ + s) * D_;
        uint32_t hw, lw;
        pack_hilo_h(o0, o1, hw, lw);
        *(uint32_t*)(outh + base + d0) = hw;
        *(uint32_t*)(outl + base + d0) = lw;
        pack_hilo_h(o2, o3, hw, lw);
        *(uint32_t*)(outh + base + 64 + d0) = hw;
        *(uint32_t*)(outl + base + 64 + d0) = lw;
    }
}

/* ============== GEMM2: single-product fp16, f32 accum ===================== */
#define H1_SA 0
#define H1_SB (128 * 40)
#define H1_STAGE_E (384 * 40)
#define H1_STAGE_B (H1_STAGE_E * 2)
#define H1_STAGES 4
#define H1_SMEM (H1_STAGES * H1_STAGE_B)    /* 122880 B */

__global__ void __launch_bounds__(512, 1) gemm_h1(
    const __half* __restrict__ Ah, const __half* __restrict__ Bh,
    const float* __restrict__ bias, float* __restrict__ C, int N, int K)
{
    extern __shared__ __half hsmem[];
    const uint32_t sb = smem_u32(hsmem);

    const int tid  = threadIdx.x;
    const int lane = tid & 31;
    const int wid  = tid >> 5;
    const int wy   = wid >> 3;
    const int wx   = wid & 7;
    const int m0   = blockIdx.y * 128;
    const int n0   = blockIdx.x * 256;
    const int KT   = K / 32;

    const int lr = tid >> 2;
    const int lc = (tid & 3) * 8;
    const uint32_t doff = (uint32_t)(lr * 40 + lc) * 2;

    float acc[4][4][4];
#pragma unroll
    for (int mt = 0; mt < 4; mt++)
#pragma unroll
        for (int nt = 0; nt < 4; nt++)
#pragma unroll
            for (int j = 0; j < 4; j++) acc[mt][nt][j] = 0.f;

    const int a_row = wy * 64 + (lane & 15);
    const int a_col = (lane >> 4) * 8;
    const uint32_t a_off = (uint32_t)(a_row * 40 + a_col) * 2;
    const int b_row = wx * 32 + ((lane >> 4) << 3) + (lane & 7);
    const int b_col = ((lane >> 3) & 1) * 8;
    const uint32_t b_off = (uint32_t)(b_row * 40 + b_col) * 2;

#define H1_LOAD(kt, st) do {                                              \
        const int k0_ = (kt) * 32;                                        \
        const uint32_t s0_ = sb + (st) * H1_STAGE_B + doff;               \
        size_t asrc_ = (size_t)(m0 + lr) * K + k0_ + lc;                  \
        cp_async16(s0_ + H1_SA * 2, Ah + asrc_);                          \
        _Pragma("unroll")                                                 \
        for (int p_ = 0; p_ < 2; p_++) {                                  \
            size_t bsrc_ = (size_t)(n0 + p_ * 128 + lr) * K + k0_ + lc;   \
            cp_async16(s0_ + (H1_SB + p_ * 128 * 40) * 2, Bh + bsrc_);    \
        }                                                                 \
    } while (0)

    H1_LOAD(0, 0); CP_COMMIT();
    H1_LOAD(1, 1); CP_COMMIT();
    H1_LOAD(2, 2); CP_COMMIT();

    int st = 0;
    for (int kt = 0; kt < KT; kt++) {
        if (kt + 2 < KT)      { CP_WAIT(2); }
        else if (kt + 1 < KT) { CP_WAIT(1); }
        else                  { CP_WAIT(0); }
        __syncthreads();
        if (kt + 3 < KT) {
            int st3 = st + 3; if (st3 >= H1_STAGES) st3 -= H1_STAGES;
            H1_LOAD(kt + 3, st3);
            CP_COMMIT();
        }

        const uint32_t stb = sb + st * H1_STAGE_B;
#pragma unroll
        for (int ks = 0; ks < 32; ks += 16) {
            const uint32_t kso = (uint32_t)ks * 2;
            uint32_t bh[4][2];
#pragma unroll
            for (int nt2 = 0; nt2 < 2; nt2++) {
                uint32_t bo = stb + (H1_SB * 2) + b_off +
                              (uint32_t)(nt2 * 16 * 40) * 2 + kso;
                uint32_t r[4];
                ldsm4(r, bo);
                bh[nt2 * 2][0] = r[0]; bh[nt2 * 2][1] = r[1];
                bh[nt2 * 2 + 1][0] = r[2]; bh[nt2 * 2 + 1][1] = r[3];
            }
#pragma unroll
            for (int mt = 0; mt < 4; mt++) {
                uint32_t ah[4];
                uint32_t ao = stb + a_off + (uint32_t)(mt * 16 * 40) * 2 + kso;
                ldsm4(ah, ao);
#pragma unroll
                for (int nt = 0; nt < 4; nt++)
                    mma_h_f32(acc[mt][nt], ah, bh[nt]);
            }
        }
        st++; if (st >= H1_STAGES) st -= H1_STAGES;
    }
#undef H1_LOAD

#pragma unroll
    for (int mt = 0; mt < 4; mt++) {
        int row0 = m0 + wy * 64 + mt * 16 + (lane >> 2);
#pragma unroll
        for (int nt = 0; nt < 4; nt++) {
            int col = n0 + wx * 32 + nt * 8 + (lane & 3) * 2;
            float b0 = bias[col], b1 = bias[col + 1];
            float2 v0 = {acc[mt][nt][0] + b0, acc[mt][nt][1] + b1};
            float2 v1 = {acc[mt][nt][2] + b0, acc[mt][nt][3] + b1};
            *(float2*)(C + (size_t)row0 * N + col)       = v0;
            *(float2*)(C + (size_t)(row0 + 8) * N + col) = v1;
        }
    }
}

/* ============ HMMA flash attention: QK fp16x3, PV fp16x1 ================== */
#define AT_PAD 136
#define AQ_L   (128 * AT_PAD)
#define AST0   (2 * 128 * AT_PAD)
#define AMAT   (64 * AT_PAD)
#define ASTAGE (3 * AMAT)
#define ATTN_SMEM_B ((AST0 + 2 * ASTAGE) * 2)   /* 174080 B */
#define LOG2E 1.4426950408889634f

__global__ void __launch_bounds__(256, 1) attn_mma()
{
    const int qbx = blockIdx.x, h = blockIdx.y, b = blockIdx.z;
    const int kvh = h >> 2;
    const int qlo = qbx * 128;

    extern __shared__ __half asmem[];
    const uint32_t sb = smem_u32(asmem);
    const int tid = threadIdx.x, lane = tid & 31, w = tid >> 5;

    const __half* Qhg = g_qh + (((size_t)b * NH_ + h) * S_ + qlo) * D_;
    const __half* Qlg = g_ql + (((size_t)b * NH_ + h) * S_ + qlo) * D_;
    const __half* Khg = g_kh + ((size_t)b * NKV_ + kvh) * S_ * D_;
    const __half* Klg = g_kl + ((size_t)b * NKV_ + kvh) * S_ * D_;
    const __half* Vg  = g_v  + ((size_t)b * NKV_ + kvh) * S_ * D_;

    for (int c = tid; c < 2048; c += 256) {
        int row = c >> 4, ch = c & 15;
        uint32_t dq = sb + (uint32_t)(row * AT_PAD + ch * 8) * 2;
        size_t src = (size_t)row * D_ + ch * 8;
        cp_async16(dq, Qhg + src);
        cp_async16(dq + AQ_L * 2, Qlg + src);
    }

#define LOAD_KV(kb, st) do {                                            \
        const int kbase_ = (kb) * 64;                                   \
        const uint32_t s0_ = sb + (uint32_t)(AST0 + (st) * ASTAGE) * 2; \
        for (int c = tid; c < 1024; c += 256) {                         \
            int row_ = c >> 4, ch_ = c & 15;                            \
            uint32_t d_ = s0_ + (uint32_t)(row_ * AT_PAD + ch_ * 8) * 2;\
            size_t src_ = (size_t)(kbase_ + row_) * D_ + ch_ * 8;       \
            cp_async16(d_,                Khg + src_);                  \
            cp_async16(d_ + AMAT * 2,     Klg + src_);                  \
            cp_async16(d_ + 2 * AMAT * 2, Vg  + src_);                  \
        } } while (0)

    int kstart = qlo - (WINDOW_ - 1);
    if (kstart < 0) kstart = 0;
    const int kb0 = kstart >> 6;
    const int kb1 = (qlo + 127) >> 6;

    LOAD_KV(kb0, 0);
    CP_COMMIT();

    float oacc[16][4];
#pragma unroll
    for (int nf = 0; nf < 16; nf++)
#pragma unroll
        for (int j = 0; j < 4; j++) oacc[nf][j] = 0.f;
    float m0 = -1e30f, m1 = -1e30f, l0 = 0.f, l1 = 0.f;

    const int qg0 = qlo + w * 16 + (lane >> 2);
    const int qg1 = qg0 + 8;
    const uint32_t qrow_off =
        (uint32_t)((w * 16 + (lane & 15)) * AT_PAD + (lane >> 4) * 8) * 2;
    const uint32_t krow_off =
        (uint32_t)((((lane >> 4) << 3) + (lane & 7)) * AT_PAD +
                   ((lane >> 3) & 1) * 8) * 2;
    const uint32_t vrow_off =
        (uint32_t)((lane & 15) * AT_PAD + (lane >> 4) * 8) * 2;

    for (int kb = kb0; kb <= kb1; kb++) {
        const int st = (kb - kb0) & 1;
        if (kb < kb1) {
            LOAD_KV(kb + 1, st ^ 1);
            CP_COMMIT();
            CP_WAIT(1);
        } else {
            CP_WAIT(0);
        }
        __syncthreads();

        const uint32_t stb = sb + (uint32_t)(AST0 + st * ASTAGE) * 2;
        const int kbase = kb * 64;

        float sacc[8][4];
#pragma unroll
        for (int j = 0; j < 8; j++)
#pragma unroll
            for (int i = 0; i < 4; i++) sacc[j][i] = 0.f;

#pragma unroll
        for (int kk = 0; kk < 8; kk++) {
            uint32_t qh[4], ql[4];
            const uint32_t qoff = sb + qrow_off + kk * 32;
            ldsm4(qh, qoff);
            ldsm4(ql, qoff + AQ_L * 2);
#pragma unroll
            for (int nb = 0; nb < 4; nb++) {
                uint32_t kh[4], kl[4];
                const uint32_t koff = stb + krow_off +
                    (uint32_t)(nb * 16 * AT_PAD) * 2 + kk * 32;
                ldsm4(kh, koff);
                ldsm4(kl, koff + AMAT * 2);
                mma_h_f32(sacc[2 * nb],     qh, kh);
                mma_h_f32(sacc[2 * nb],     qh, kl);
                mma_h_f32(sacc[2 * nb],     ql, kh);
                mma_h_f32(sacc[2 * nb + 1], qh, &kh[2]);
                mma_h_f32(sacc[2 * nb + 1], qh, &kl[2]);
                mma_h_f32(sacc[2 * nb + 1], ql, &kh[2]);
            }
        }

#pragma unroll
        for (int j = 0; j < 8; j++) {
            const int kg0 = kbase + 8 * j + 2 * (lane & 3);
            const int kg1 = kg0 + 1;
            if (!(kg0 <= qg0 && qg0 - kg0 < WINDOW_)) sacc[j][0] = -1e30f;
            if (!(kg1 <= qg0 && qg0 - kg1 < WINDOW_)) sacc[j][1] = -1e30f;
            if (!(kg0 <= qg1 && qg1 - kg0 < WINDOW_)) sacc[j][2] = -1e30f;
            if (!(kg1 <= qg1 && qg1 - kg1 < WINDOW_)) sacc[j][3] = -1e30f;
        }

        float mx0 = m0, mx1 = m1;
#pragma unroll
        for (int j = 0; j < 8; j++) {
            mx0 = fmaxf(mx0, fmaxf(sacc[j][0], sacc[j][1]));
            mx1 = fmaxf(mx1, fmaxf(sacc[j][2], sacc[j][3]));
        }
        mx0 = fmaxf(mx0, __shfl_xor_sync(0xffffffffu, mx0, 1));
        mx0 = fmaxf(mx0, __shfl_xor_sync(0xffffffffu, mx0, 2));
        mx1 = fmaxf(mx1, __shfl_xor_sync(0xffffffffu, mx1, 1));
        mx1 = fmaxf(mx1, __shfl_xor_sync(0xffffffffu, mx1, 2));

        const float sc0 = ex2f((m0 - mx0) * LOG2E);
        const float sc1 = ex2f((m1 - mx1) * LOG2E);
        float la0 = 0.f, la1 = 0.f;
#pragma unroll
        for (int j = 0; j < 8; j++) {
            float p0 = (sacc[j][0] > -1e29f) ? ex2f((sacc[j][0] - mx0) * LOG2E) : 0.f;
            float p1 = (sacc[j][1] > -1e29f) ? ex2f((sacc[j][1] - mx0) * LOG2E) : 0.f;
            float p2 = (sacc[j][2] > -1e29f) ? ex2f((sacc[j][2] - mx1) * LOG2E) : 0.f;
            float p3 = (sacc[j][3] > -1e29f) ? ex2f((sacc[j][3] - mx1) * LOG2E) : 0.f;
            sacc[j][0] = p0; sacc[j][1] = p1; sacc[j][2] = p2; sacc[j][3] = p3;
            la0 += p0 + p1;
            la1 += p2 + p3;
        }
        la0 += __shfl_xor_sync(0xffffffffu, la0, 1);
        la0 += __shfl_xor_sync(0xffffffffu, la0, 2);
        la1 += __shfl_xor_sync(0xffffffffu, la1, 1);
        la1 += __shfl_xor_sync(0xffffffffu, la1, 2);
        l0 = l0 * sc0 + la0;
        l1 = l1 * sc1 + la1;
        m0 = mx0; m1 = mx1;

#pragma unroll
        for (int nf = 0; nf < 16; nf++) {
            oacc[nf][0] *= sc0; oacc[nf][1] *= sc0;
            oacc[nf][2] *= sc1; oacc[nf][3] *= sc1;
        }

#pragma unroll
        for (int s4 = 0; s4 < 4; s4++) {
            uint32_t ah[4];
            ah[0] = pack_h(sacc[2 * s4][0],     sacc[2 * s4][1]);
            ah[1] = pack_h(sacc[2 * s4][2],     sacc[2 * s4][3]);
            ah[2] = pack_h(sacc[2 * s4 + 1][0], sacc[2 * s4 + 1][1]);
            ah[3] = pack_h(sacc[2 * s4 + 1][2], sacc[2 * s4 + 1][3]);

            const uint32_t vbase = stb + 2 * AMAT * 2 + vrow_off +
                                   (uint32_t)(s4 * 16 * AT_PAD) * 2;
#pragma unroll
            for (int db = 0; db < 8; db++) {
                uint32_t vh[4];
                ldsm4t(vh, vbase + db * 32);
                mma_h_f32(oacc[2 * db],     ah, vh);
                mma_h_f32(oacc[2 * db + 1], ah, &vh[2]);
            }
        }
        __syncthreads();
    }
#undef LOAD_KV

    const float inv0 = 1.f / l0;
    const float inv1 = 1.f / l1;
    const size_t o0 = (size_t)(b * S_ + qg0) * (NH_ * D_) + h * D_;
    const size_t o1 = (size_t)(b * S_ + qg1) * (NH_ * D_) + h * D_;
#pragma unroll
    for (int nf = 0; nf < 16; nf++) {
        const int dc = 8 * nf + 2 * (lane & 3);
        *(uint32_t*)(g_at_h + o0 + dc) =
            pack_h(oacc[nf][0] * inv0, oacc[nf][1] * inv0);
        *(uint32_t*)(g_at_h + o1 + dc) =
            pack_h(oacc[nf][2] * inv1, oacc[nf][3] * inv1);
    }
}

/* --------------------------------- launch --------------------------------- */
extern "C" void kernel_launch(void* const* d_in, const int* in_sizes, int n_in,
                              void* d_out, int out_size)
{
    const float* hidden = (const float*)d_in[0];
    const float* cosp   = (const float*)d_in[1];
    const float* sinp   = (const float*)d_in[2];
    const float* w_qkv  = (const float*)d_in[3];
    const float* b_qkv  = (const float*)d_in[4];
    const float* w_o    = (const float*)d_in[5];
    const float* b_o    = (const float*)d_in[6];
    float* out = (float*)d_out;

    __half *p_h_hi, *p_h_lo, *p_wq_hi, *p_wq_lo, *p_wo_h, *p_at_h;
    cudaGetSymbolAddress((void**)&p_h_hi, g_h_hi);
    cudaGetSymbolAddress((void**)&p_h_lo, g_h_lo);
    cudaGetSymbolAddress((void**)&p_wq_hi, g_wq_hi);
    cudaGetSymbolAddress((void**)&p_wq_lo, g_wq_lo);
    cudaGetSymbolAddress((void**)&p_wo_h, g_wo_h);
    cudaGetSymbolAddress((void**)&p_at_h, g_at_h);

    cudaFuncSetAttribute(gemm1_u,
                         cudaFuncAttributeMaxDynamicSharedMemorySize, G1_SMEM);
    cudaFuncSetAttribute(gemm_h1,
                         cudaFuncAttributeMaxDynamicSharedMemorySize, H1_SMEM);
    cudaFuncSetAttribute(attn_mma,
                         cudaFuncAttributeMaxDynamicSharedMemorySize, ATTN_SMEM_B);

    /* converts */
    cvt_split_h<<<(BS_ * HID_ / 4 + 255) / 256, 256>>>(hidden, p_h_hi, p_h_lo,
                                                       BS_ * HID_ / 4);
    cvt_split_h<<<(QKV_OUT_ * HID_ / 4 + 255) / 256, 256>>>(w_qkv, p_wq_hi,
                                                            p_wq_lo,
                                                            QKV_OUT_ * HID_ / 4);
    cvt_h<<<(HID_ * HID_ / 4 + 255) / 256, 256>>>(w_o, p_wo_h,
                                                  HID_ * HID_ / 4);

    /* 1) dual-path qkv GEMM, fine 128x128 tiles for SM balance */
    gemm1_u<<<dim3(QKV_OUT_ / 128, BS_ / 128), 256, G1_SMEM>>>(
        p_h_hi, p_h_lo, p_wq_hi, p_wq_lo, b_qkv, cosp, sinp, HID_);

    /* 2) flash attention (QK fp16x3, PV fp16x1) */
    attn_mma<<<dim3(S_ / 128, NH_, B_), 256, ATTN_SMEM_B>>>();

    /* 3) out = attn @ w_o^T + b_o (single-product fp16) */
    gemm_h1<<<dim3(HID_ / 256, BS_ / 128), 512, H1_SMEM>>>(
        p_at_h, p_wo_h, b_o, out, HID_, HID_);
}

// round 17
// speedup vs baseline: 2.2102x; 1.0112x over previous
#include <cuda_runtime.h>
#include <cuda_fp16.h>
#include <cstdint>
#include <math.h>

#define B_ 2
#define S_ 1024
#define HID_ 4096
#define NH_ 32
#define NKV_ 8
#define D_ 128
#define WINDOW_ 512
#define QKV_OUT_ ((NH_ + 2 * NKV_) * D_)   /* 6144 */
#define BS_ (B_ * S_)                      /* 2048 */
#define VSTART_ ((NH_ + NKV_) * D_)        /* 5120 */

/* ------------------------- scratch (static device globals) ---------------- */
__device__ __half g_qh[B_ * NH_ * S_ * D_];
__device__ __half g_ql[B_ * NH_ * S_ * D_];
__device__ __half g_kh[B_ * NKV_ * S_ * D_];
__device__ __half g_kl[B_ * NKV_ * S_ * D_];
__device__ __half g_v [B_ * NKV_ * S_ * D_];

__device__ __half g_h_hi[BS_ * HID_];
__device__ __half g_h_lo[BS_ * HID_];
__device__ __half g_wq_hi[QKV_OUT_ * HID_];
__device__ __half g_wq_lo[QKV_OUT_ * HID_];
__device__ __half g_wo_h[HID_ * HID_];
__device__ __half g_at_h[BS_ * HID_];

/* ============================ PTX helpers (base ISA only) ================= */
__device__ __forceinline__ uint32_t smem_u32(const void* p) {
    return (uint32_t)__cvta_generic_to_shared(p);
}
__device__ __forceinline__ void cp_async16(uint32_t dst, const void* src) {
    asm volatile("cp.async.cg.shared.global [%0], [%1], 16;\n"
                 :: "r"(dst), "l"(src));
}
#define CP_COMMIT() asm volatile("cp.async.commit_group;\n" ::: "memory")
#define CP_WAIT(n)  asm volatile("cp.async.wait_group %0;\n" :: "n"(n) : "memory")

__device__ __forceinline__ void ldsm4(uint32_t* r, uint32_t addr) {
    asm volatile("ldmatrix.sync.aligned.m8n8.x4.shared.b16 {%0,%1,%2,%3}, [%4];"
                 : "=r"(r[0]), "=r"(r[1]), "=r"(r[2]), "=r"(r[3]) : "r"(addr));
}
__device__ __forceinline__ void ldsm4t(uint32_t* r, uint32_t addr) {
    asm volatile("ldmatrix.sync.aligned.m8n8.x4.trans.shared.b16 {%0,%1,%2,%3}, [%4];"
                 : "=r"(r[0]), "=r"(r[1]), "=r"(r[2]), "=r"(r[3]) : "r"(addr));
}
__device__ __forceinline__ void mma_h_f32(float* d, const uint32_t* a,
                                          const uint32_t* b) {
    asm volatile("mma.sync.aligned.m16n8k16.row.col.f32.f16.f16.f32 "
                 "{%0,%1,%2,%3}, {%4,%5,%6,%7}, {%8,%9}, {%0,%1,%2,%3};"
                 : "+f"(d[0]), "+f"(d[1]), "+f"(d[2]), "+f"(d[3])
                 : "r"(a[0]), "r"(a[1]), "r"(a[2]), "r"(a[3]),
                   "r"(b[0]), "r"(b[1]));
}
__device__ __forceinline__ float ex2f(float x) {
    float y;
    asm("ex2.approx.f32 %0, %1;" : "=f"(y) : "f"(x));
    return y;
}
__device__ __forceinline__ void pack_hilo_h(float x, float y,
                                            uint32_t& hw, uint32_t& lw) {
    __half2 h = __floats2half2_rn(x, y);
    float2 hf = __half22float2(h);
    __half2 l = __floats2half2_rn(x - hf.x, y - hf.y);
    hw = *(uint32_t*)&h;
    lw = *(uint32_t*)&l;
}
__device__ __forceinline__ uint32_t pack_h(float x, float y) {
    __half2 h = __floats2half2_rn(x, y);
    return *(uint32_t*)&h;
}

/* ============ merged converts: hidden+w_qkv split, w_o single ============= */
#define CV_N1 (BS_ * HID_ / 4)
#define CV_N2 (CV_N1 + QKV_OUT_ * HID_ / 4)
#define CV_N3 (CV_N2 + HID_ * HID_ / 4)

__global__ void cvt_all(const float* __restrict__ hidden,
                        const float* __restrict__ wqkv,
                        const float* __restrict__ wo)
{
    int i = blockIdx.x * blockDim.x + threadIdx.x;
    if (i < CV_N1) {
        float4 v = ((const float4*)hidden)[i];
        uint2 hw, lw;
        uint32_t a, b;
        pack_hilo_h(v.x, v.y, a, b); hw.x = a; lw.x = b;
        pack_hilo_h(v.z, v.w, a, b); hw.y = a; lw.y = b;
        ((uint2*)g_h_hi)[i] = hw;
        ((uint2*)g_h_lo)[i] = lw;
    } else if (i < CV_N2) {
        int j = i - CV_N1;
        float4 v = ((const float4*)wqkv)[j];
        uint2 hw, lw;
        uint32_t a, b;
        pack_hilo_h(v.x, v.y, a, b); hw.x = a; lw.x = b;
        pack_hilo_h(v.z, v.w, a, b); hw.y = a; lw.y = b;
        ((uint2*)g_wq_hi)[j] = hw;
        ((uint2*)g_wq_lo)[j] = lw;
    } else if (i < CV_N3) {
        int j = i - CV_N2;
        float4 v = ((const float4*)wo)[j];
        uint2 hw;
        hw.x = pack_h(v.x, v.y);
        hw.y = pack_h(v.z, v.w);
        ((uint2*)g_wo_h)[j] = hw;
    }
}

/* ====== GEMM1: 128x128 tiles, dual-path (QK fp16x3+RoPE | V fp16x1) ====== */
#define G1_SA_HI 0
#define G1_SA_LO (128 * 40)
#define G1_SB_HI (2 * 128 * 40)
#define G1_SB_LO (3 * 128 * 40)
#define G1_STAGE_E (4 * 128 * 40)
#define G1_STAGE_B (G1_STAGE_E * 2)        /* 40960 B */
#define G1_STAGES 3
#define G1_SMEM (G1_STAGES * G1_STAGE_B)   /* 122880 B */
#define G1_CP 132

__global__ void __launch_bounds__(256, 1) gemm1_u(
    const __half* __restrict__ Ah, const __half* __restrict__ Al,
    const __half* __restrict__ Bh, const __half* __restrict__ Bl,
    const float* __restrict__ bias,
    const float* __restrict__ cosp, const float* __restrict__ sinp,
    int K)
{
    extern __shared__ __half smem[];
    const uint32_t sb = smem_u32(smem);

    const int tid  = threadIdx.x;
    const int lane = tid & 31;
    const int wid  = tid >> 5;
    const int wy   = wid >> 2;
    const int wx   = wid & 3;
    const int m0   = blockIdx.y * 128;
    const int n0   = blockIdx.x * 128;
    const int KT   = K / 32;

    const int lr = tid >> 2;
    const int lc = (tid & 3) * 8;
    const uint32_t doff = (uint32_t)(lr * 40 + lc) * 2;
#define ROW2 (64 * 40 * 2)

    const uint32_t a_off = (uint32_t)((wy * 64 + (lane & 15)) * 40 +
                                      (lane >> 4) * 8) * 2;
    const uint32_t b_off = (uint32_t)((wx * 32 + ((lane >> 4) << 3) +
                                       (lane & 7)) * 40 +
                                      ((lane >> 3) & 1) * 8) * 2;

    float acc[4][4][4];
#pragma unroll
    for (int mt = 0; mt < 4; mt++)
#pragma unroll
        for (int nt = 0; nt < 4; nt++)
#pragma unroll
            for (int j = 0; j < 4; j++) acc[mt][nt][j] = 0.f;

    if (n0 >= VSTART_) {
        /* ---------------- V path: single product ------------------------ */
#define V_LOAD(kt, st) do {                                                \
        const int k0_ = (kt) * 32;                                         \
        const uint32_t s0_ = sb + (st) * G1_STAGE_B + doff;                \
        size_t a0_ = (size_t)(m0 + lr) * K + k0_ + lc;                     \
        size_t a1_ = (size_t)(m0 + 64 + lr) * K + k0_ + lc;                \
        size_t b0_ = (size_t)(n0 + lr) * K + k0_ + lc;                     \
        size_t b1_ = (size_t)(n0 + 64 + lr) * K + k0_ + lc;                \
        cp_async16(s0_ + G1_SA_HI * 2,        Ah + a0_);                   \
        cp_async16(s0_ + G1_SA_HI * 2 + ROW2, Ah + a1_);                   \
        cp_async16(s0_ + G1_SB_HI * 2,        Bh + b0_);                   \
        cp_async16(s0_ + G1_SB_HI * 2 + ROW2, Bh + b1_);                   \
    } while (0)

        V_LOAD(0, 0); CP_COMMIT();
        V_LOAD(1, 1); CP_COMMIT();

        int st = 0;
        for (int kt = 0; kt < KT; kt++) {
            if (kt + 1 < KT) { CP_WAIT(1); } else { CP_WAIT(0); }
            __syncthreads();
            if (kt + 2 < KT) {
                int st2 = st + 2; if (st2 >= G1_STAGES) st2 -= G1_STAGES;
                V_LOAD(kt + 2, st2);
                CP_COMMIT();
            }

            const uint32_t stb = sb + st * G1_STAGE_B;
#pragma unroll
            for (int ks = 0; ks < 32; ks += 16) {
                const uint32_t kso = (uint32_t)ks * 2;
                uint32_t bh[4][2];
#pragma unroll
                for (int nt2 = 0; nt2 < 2; nt2++) {
                    uint32_t bo = stb + b_off +
                                  (uint32_t)(nt2 * 16 * 40) * 2 + kso;
                    uint32_t r[4];
                    ldsm4(r, bo + G1_SB_HI * 2);
                    bh[nt2 * 2][0] = r[0]; bh[nt2 * 2][1] = r[1];
                    bh[nt2 * 2 + 1][0] = r[2]; bh[nt2 * 2 + 1][1] = r[3];
                }
#pragma unroll
                for (int mt = 0; mt < 4; mt++) {
                    uint32_t ah[4];
                    uint32_t ao = stb + a_off +
                                  (uint32_t)(mt * 16 * 40) * 2 + kso;
                    ldsm4(ah, ao + G1_SA_HI * 2);
#pragma unroll
                    for (int nt = 0; nt < 4; nt++)
                        mma_h_f32(acc[mt][nt], ah, bh[nt]);
                }
            }
            st++; if (st >= G1_STAGES) st -= G1_STAGES;
        }
#undef V_LOAD

        const int kvh = (n0 - VSTART_) >> 7;
#pragma unroll
        for (int mt = 0; mt < 4; mt++) {
            int row0 = m0 + wy * 64 + mt * 16 + (lane >> 2);
            int bb0 = row0 >> 10, s0r = row0 & 1023;
            int row1 = row0 + 8;
            int bb1 = row1 >> 10, s1r = row1 & 1023;
#pragma unroll
            for (int nt = 0; nt < 4; nt++) {
                int col = n0 + wx * 32 + nt * 8 + (lane & 3) * 2;
                int d0 = col & 127;
                float b0 = bias[col], b1 = bias[col + 1];
                size_t base0 = (((size_t)bb0 * NKV_ + kvh) * S_ + s0r) * D_ + d0;
                size_t base1 = (((size_t)bb1 * NKV_ + kvh) * S_ + s1r) * D_ + d0;
                *(uint32_t*)(g_v + base0) =
                    pack_h(acc[mt][nt][0] + b0, acc[mt][nt][1] + b1);
                *(uint32_t*)(g_v + base1) =
                    pack_h(acc[mt][nt][2] + b0, acc[mt][nt][3] + b1);
            }
        }
        return;
    }

    /* ---------------- QK path: 3-product + fused RoPE -------------------- */
#define QK_LOAD(kt, st) do {                                               \
        const int k0_ = (kt) * 32;                                         \
        const uint32_t s0_ = sb + (st) * G1_STAGE_B + doff;                \
        size_t a0_ = (size_t)(m0 + lr) * K + k0_ + lc;                     \
        size_t a1_ = (size_t)(m0 + 64 + lr) * K + k0_ + lc;                \
        size_t b0_ = (size_t)(n0 + lr) * K + k0_ + lc;                     \
        size_t b1_ = (size_t)(n0 + 64 + lr) * K + k0_ + lc;                \
        cp_async16(s0_ + G1_SA_HI * 2,        Ah + a0_);                   \
        cp_async16(s0_ + G1_SA_HI * 2 + ROW2, Ah + a1_);                   \
        cp_async16(s0_ + G1_SA_LO * 2,        Al + a0_);                   \
        cp_async16(s0_ + G1_SA_LO * 2 + ROW2, Al + a1_);                   \
        cp_async16(s0_ + G1_SB_HI * 2,        Bh + b0_);                   \
        cp_async16(s0_ + G1_SB_HI * 2 + ROW2, Bh + b1_);                   \
        cp_async16(s0_ + G1_SB_LO * 2,        Bl + b0_);                   \
        cp_async16(s0_ + G1_SB_LO * 2 + ROW2, Bl + b1_);                   \
    } while (0)

    QK_LOAD(0, 0); CP_COMMIT();
    QK_LOAD(1, 1); CP_COMMIT();

    int st = 0;
    for (int kt = 0; kt < KT; kt++) {
        if (kt + 1 < KT) { CP_WAIT(1); } else { CP_WAIT(0); }
        __syncthreads();
        if (kt + 2 < KT) {
            int st2 = st + 2; if (st2 >= G1_STAGES) st2 -= G1_STAGES;
            QK_LOAD(kt + 2, st2);
            CP_COMMIT();
        }

        const uint32_t stb = sb + st * G1_STAGE_B;
#pragma unroll
        for (int ks = 0; ks < 32; ks += 16) {
            const uint32_t kso = (uint32_t)ks * 2;
            uint32_t bh[4][2], bl[4][2];
#pragma unroll
            for (int nt2 = 0; nt2 < 2; nt2++) {
                uint32_t bo = stb + b_off + (uint32_t)(nt2 * 16 * 40) * 2 + kso;
                uint32_t r[4];
                ldsm4(r, bo + G1_SB_HI * 2);
                bh[nt2 * 2][0] = r[0]; bh[nt2 * 2][1] = r[1];
                bh[nt2 * 2 + 1][0] = r[2]; bh[nt2 * 2 + 1][1] = r[3];
                ldsm4(r, bo + G1_SB_LO * 2);
                bl[nt2 * 2][0] = r[0]; bl[nt2 * 2][1] = r[1];
                bl[nt2 * 2 + 1][0] = r[2]; bl[nt2 * 2 + 1][1] = r[3];
            }
#pragma unroll
            for (int mt = 0; mt < 4; mt++) {
                uint32_t ah[4], al[4];
                uint32_t ao = stb + a_off + (uint32_t)(mt * 16 * 40) * 2 + kso;
                ldsm4(ah, ao + G1_SA_HI * 2);
                ldsm4(al, ao + G1_SA_LO * 2);
#pragma unroll
                for (int nt = 0; nt < 4; nt++)
                    mma_h_f32(acc[mt][nt], ah, bh[nt]);
#pragma unroll
                for (int nt = 0; nt < 4; nt++)
                    mma_h_f32(acc[mt][nt], ah, bl[nt]);
#pragma unroll
                for (int nt = 0; nt < 4; nt++)
                    mma_h_f32(acc[mt][nt], al, bh[nt]);
            }
        }
        st++; if (st >= G1_STAGES) st -= G1_STAGES;
    }
#undef QK_LOAD

    __syncthreads();
    float* sC = (float*)smem;
#pragma unroll
    for (int mt = 0; mt < 4; mt++) {
        int r0 = wy * 64 + mt * 16 + (lane >> 2);
#pragma unroll
        for (int nt = 0; nt < 4; nt++) {
            int cl = wx * 32 + nt * 8 + (lane & 3) * 2;
            float b0 = bias[n0 + cl], b1 = bias[n0 + cl + 1];
            *(float2*)&sC[r0 * G1_CP + cl] =
                make_float2(acc[mt][nt][0] + b0, acc[mt][nt][1] + b1);
            *(float2*)&sC[(r0 + 8) * G1_CP + cl] =
                make_float2(acc[mt][nt][2] + b0, acc[mt][nt][3] + b1);
        }
    }
    __syncthreads();

    const float SCALE = 0.08838834764831845f;
    const bool isQ = (n0 < NH_ * D_);
    const int head = isQ ? (n0 >> 7) : ((n0 - NH_ * D_) >> 7);
    __half* outh = isQ ? g_qh : g_kh;
    __half* outl = isQ ? g_ql : g_kl;
    const int nheads = isQ ? NH_ : NKV_;
    const float qsc = isQ ? SCALE : 1.f;

    for (int e = tid; e < 4096; e += 256) {
        int i = e & 31;
        int r = e >> 5;
        int d0 = 2 * i;
        int row = m0 + r;
        int bb = row >> 10, s = row & 1023;

        float2 vlo = *(float2*)&sC[r * G1_CP + d0];
        float2 vhi = *(float2*)&sC[r * G1_CP + 64 + d0];
        float2 c_lo = *(const float2*)&cosp[s * D_ + d0];
        float2 c_hi = *(const float2*)&cosp[s * D_ + 64 + d0];
        float2 s_lo = *(const float2*)&sinp[s * D_ + d0];
        float2 s_hi = *(const float2*)&sinp[s * D_ + 64 + d0];

        float o0 = (vlo.x * c_lo.x - vhi.x * s_lo.x) * qsc;
        float o1 = (vlo.y * c_lo.y - vhi.y * s_lo.y) * qsc;
        float o2 = (vhi.x * c_hi.x + vlo.x * s_hi.x) * qsc;
        float o3 = (vhi.y * c_hi.y + vlo.y * s_hi.y) * qsc;
        size_t base = (((size_t)bb * nheads + head) * S_ + s) * D_;
        uint32_t hw, lw;
        pack_hilo_h(o0, o1, hw, lw);
        *(uint32_t*)(outh + base + d0) = hw;
        *(uint32_t*)(outl + base + d0) = lw;
        pack_hilo_h(o2, o3, hw, lw);
        *(uint32_t*)(outh + base + 64 + d0) = hw;
        *(uint32_t*)(outl + base + 64 + d0) = lw;
    }
}

/* ============== GEMM2: single-product fp16, f32 accum ===================== */
#define H1_SA 0
#define H1_SB (128 * 40)
#define H1_STAGE_E (384 * 40)
#define H1_STAGE_B (H1_STAGE_E * 2)
#define H1_STAGES 4
#define H1_SMEM (H1_STAGES * H1_STAGE_B)    /* 122880 B */

__global__ void __launch_bounds__(512, 1) gemm_h1(
    const __half* __restrict__ Ah, const __half* __restrict__ Bh,
    const float* __restrict__ bias, float* __restrict__ C, int N, int K)
{
    extern __shared__ __half hsmem[];
    const uint32_t sb = smem_u32(hsmem);

    const int tid  = threadIdx.x;
    const int lane = tid & 31;
    const int wid  = tid >> 5;
    const int wy   = wid >> 3;
    const int wx   = wid & 7;
    const int m0   = blockIdx.y * 128;
    const int n0   = blockIdx.x * 256;
    const int KT   = K / 32;

    const int lr = tid >> 2;
    const int lc = (tid & 3) * 8;
    const uint32_t doff = (uint32_t)(lr * 40 + lc) * 2;

    float acc[4][4][4];
#pragma unroll
    for (int mt = 0; mt < 4; mt++)
#pragma unroll
        for (int nt = 0; nt < 4; nt++)
#pragma unroll
            for (int j = 0; j < 4; j++) acc[mt][nt][j] = 0.f;

    const int a_row = wy * 64 + (lane & 15);
    const int a_col = (lane >> 4) * 8;
    const uint32_t a_off = (uint32_t)(a_row * 40 + a_col) * 2;
    const int b_row = wx * 32 + ((lane >> 4) << 3) + (lane & 7);
    const int b_col = ((lane >> 3) & 1) * 8;
    const uint32_t b_off = (uint32_t)(b_row * 40 + b_col) * 2;

#define H1_LOAD(kt, st) do {                                              \
        const int k0_ = (kt) * 32;                                        \
        const uint32_t s0_ = sb + (st) * H1_STAGE_B + doff;               \
        size_t asrc_ = (size_t)(m0 + lr) * K + k0_ + lc;                  \
        cp_async16(s0_ + H1_SA * 2, Ah + asrc_);                          \
        _Pragma("unroll")                                                 \
        for (int p_ = 0; p_ < 2; p_++) {                                  \
            size_t bsrc_ = (size_t)(n0 + p_ * 128 + lr) * K + k0_ + lc;   \
            cp_async16(s0_ + (H1_SB + p_ * 128 * 40) * 2, Bh + bsrc_);    \
        }                                                                 \
    } while (0)

    H1_LOAD(0, 0); CP_COMMIT();
    H1_LOAD(1, 1); CP_COMMIT();
    H1_LOAD(2, 2); CP_COMMIT();

    int st = 0;
    for (int kt = 0; kt < KT; kt++) {
        if (kt + 2 < KT)      { CP_WAIT(2); }
        else if (kt + 1 < KT) { CP_WAIT(1); }
        else                  { CP_WAIT(0); }
        __syncthreads();
        if (kt + 3 < KT) {
            int st3 = st + 3; if (st3 >= H1_STAGES) st3 -= H1_STAGES;
            H1_LOAD(kt + 3, st3);
            CP_COMMIT();
        }

        const uint32_t stb = sb + st * H1_STAGE_B;
#pragma unroll
        for (int ks = 0; ks < 32; ks += 16) {
            const uint32_t kso = (uint32_t)ks * 2;
            uint32_t bh[4][2];
#pragma unroll
            for (int nt2 = 0; nt2 < 2; nt2++) {
                uint32_t bo = stb + (H1_SB * 2) + b_off +
                              (uint32_t)(nt2 * 16 * 40) * 2 + kso;
                uint32_t r[4];
                ldsm4(r, bo);
                bh[nt2 * 2][0] = r[0]; bh[nt2 * 2][1] = r[1];
                bh[nt2 * 2 + 1][0] = r[2]; bh[nt2 * 2 + 1][1] = r[3];
            }
#pragma unroll
            for (int mt = 0; mt < 4; mt++) {
                uint32_t ah[4];
                uint32_t ao = stb + a_off + (uint32_t)(mt * 16 * 40) * 2 + kso;
                ldsm4(ah, ao);
#pragma unroll
                for (int nt = 0; nt < 4; nt++)
                    mma_h_f32(acc[mt][nt], ah, bh[nt]);
            }
        }
        st++; if (st >= H1_STAGES) st -= H1_STAGES;
    }
#undef H1_LOAD

#pragma unroll
    for (int mt = 0; mt < 4; mt++) {
        int row0 = m0 + wy * 64 + mt * 16 + (lane >> 2);
#pragma unroll
        for (int nt = 0; nt < 4; nt++) {
            int col = n0 + wx * 32 + nt * 8 + (lane & 3) * 2;
            float b0 = bias[col], b1 = bias[col + 1];
            float2 v0 = {acc[mt][nt][0] + b0, acc[mt][nt][1] + b1};
            float2 v1 = {acc[mt][nt][2] + b0, acc[mt][nt][3] + b1};
            *(float2*)(C + (size_t)row0 * N + col)       = v0;
            *(float2*)(C + (size_t)(row0 + 8) * N + col) = v1;
        }
    }
}

/* ============ HMMA flash attention: QK fp16x3, PV fp16x1 ================== */
/* Per-warp key-block skip: blocks fully outside a warp's causal window are
   skipped exactly (they would contribute p=0 and sc=exp(-inf)=0 anyway).  */
#define AT_PAD 136
#define AQ_L   (128 * AT_PAD)
#define AST0   (2 * 128 * AT_PAD)
#define AMAT   (64 * AT_PAD)
#define ASTAGE (3 * AMAT)
#define ATTN_SMEM_B ((AST0 + 2 * ASTAGE) * 2)   /* 174080 B */
#define LOG2E 1.4426950408889634f

__global__ void __launch_bounds__(256, 1) attn_mma()
{
    const int qbx = blockIdx.x, h = blockIdx.y, b = blockIdx.z;
    const int kvh = h >> 2;
    const int qlo = qbx * 128;

    extern __shared__ __half asmem[];
    const uint32_t sb = smem_u32(asmem);
    const int tid = threadIdx.x, lane = tid & 31, w = tid >> 5;

    const __half* Qhg = g_qh + (((size_t)b * NH_ + h) * S_ + qlo) * D_;
    const __half* Qlg = g_ql + (((size_t)b * NH_ + h) * S_ + qlo) * D_;
    const __half* Khg = g_kh + ((size_t)b * NKV_ + kvh) * S_ * D_;
    const __half* Klg = g_kl + ((size_t)b * NKV_ + kvh) * S_ * D_;
    const __half* Vg  = g_v  + ((size_t)b * NKV_ + kvh) * S_ * D_;

    for (int c = tid; c < 2048; c += 256) {
        int row = c >> 4, ch = c & 15;
        uint32_t dq = sb + (uint32_t)(row * AT_PAD + ch * 8) * 2;
        size_t src = (size_t)row * D_ + ch * 8;
        cp_async16(dq, Qhg + src);
        cp_async16(dq + AQ_L * 2, Qlg + src);
    }

#define LOAD_KV(kb, st) do {                                            \
        const int kbase_ = (kb) * 64;                                   \
        const uint32_t s0_ = sb + (uint32_t)(AST0 + (st) * ASTAGE) * 2; \
        for (int c = tid; c < 1024; c += 256) {                         \
            int row_ = c >> 4, ch_ = c & 15;                            \
            uint32_t d_ = s0_ + (uint32_t)(row_ * AT_PAD + ch_ * 8) * 2;\
            size_t src_ = (size_t)(kbase_ + row_) * D_ + ch_ * 8;       \
            cp_async16(d_,                Khg + src_);                  \
            cp_async16(d_ + AMAT * 2,     Klg + src_);                  \
            cp_async16(d_ + 2 * AMAT * 2, Vg  + src_);                  \
        } } while (0)

    int kstart = qlo - (WINDOW_ - 1);
    if (kstart < 0) kstart = 0;
    const int kb0 = kstart >> 6;
    const int kb1 = (qlo + 127) >> 6;

    LOAD_KV(kb0, 0);
    CP_COMMIT();

    float oacc[16][4];
#pragma unroll
    for (int nf = 0; nf < 16; nf++)
#pragma unroll
        for (int j = 0; j < 4; j++) oacc[nf][j] = 0.f;
    float m0 = -1e30f, m1 = -1e30f, l0 = 0.f, l1 = 0.f;

    const int qg0 = qlo + w * 16 + (lane >> 2);
    const int qg1 = qg0 + 8;
    const int wqmin = qlo + w * 16;        /* warp's min query row */
    const int wqmax = wqmin + 15;          /* warp's max query row */
    const uint32_t qrow_off =
        (uint32_t)((w * 16 + (lane & 15)) * AT_PAD + (lane >> 4) * 8) * 2;
    const uint32_t krow_off =
        (uint32_t)((((lane >> 4) << 3) + (lane & 7)) * AT_PAD +
                   ((lane >> 3) & 1) * 8) * 2;
    const uint32_t vrow_off =
        (uint32_t)((lane & 15) * AT_PAD + (lane >> 4) * 8) * 2;

    for (int kb = kb0; kb <= kb1; kb++) {
        const int st = (kb - kb0) & 1;
        if (kb < kb1) {
            LOAD_KV(kb + 1, st ^ 1);
            CP_COMMIT();
            CP_WAIT(1);
        } else {
            CP_WAIT(0);
        }
        __syncthreads();

        const uint32_t stb = sb + (uint32_t)(AST0 + st * ASTAGE) * 2;
        const int kbase = kb * 64;

        /* per-warp skip: block entirely masked for this warp's 16 q-rows */
        const bool active = (kbase <= wqmax) &&
                            (kbase + 63 >= wqmin - (WINDOW_ - 1));
        if (active) {
            float sacc[8][4];
#pragma unroll
            for (int j = 0; j < 8; j++)
#pragma unroll
                for (int i = 0; i < 4; i++) sacc[j][i] = 0.f;

#pragma unroll
            for (int kk = 0; kk < 8; kk++) {
                uint32_t qh[4], ql[4];
                const uint32_t qoff = sb + qrow_off + kk * 32;
                ldsm4(qh, qoff);
                ldsm4(ql, qoff + AQ_L * 2);
#pragma unroll
                for (int nb = 0; nb < 4; nb++) {
                    uint32_t kh[4], kl[4];
                    const uint32_t koff = stb + krow_off +
                        (uint32_t)(nb * 16 * AT_PAD) * 2 + kk * 32;
                    ldsm4(kh, koff);
                    ldsm4(kl, koff + AMAT * 2);
                    mma_h_f32(sacc[2 * nb],     qh, kh);
                    mma_h_f32(sacc[2 * nb],     qh, kl);
                    mma_h_f32(sacc[2 * nb],     ql, kh);
                    mma_h_f32(sacc[2 * nb + 1], qh, &kh[2]);
                    mma_h_f32(sacc[2 * nb + 1], qh, &kl[2]);
                    mma_h_f32(sacc[2 * nb + 1], ql, &kh[2]);
                }
            }

#pragma unroll
            for (int j = 0; j < 8; j++) {
                const int kg0 = kbase + 8 * j + 2 * (lane & 3);
                const int kg1 = kg0 + 1;
                if (!(kg0 <= qg0 && qg0 - kg0 < WINDOW_)) sacc[j][0] = -1e30f;
                if (!(kg1 <= qg0 && qg0 - kg1 < WINDOW_)) sacc[j][1] = -1e30f;
                if (!(kg0 <= qg1 && qg1 - kg0 < WINDOW_)) sacc[j][2] = -1e30f;
                if (!(kg1 <= qg1 && qg1 - kg1 < WINDOW_)) sacc[j][3] = -1e30f;
            }

            float mx0 = m0, mx1 = m1;
#pragma unroll
            for (int j = 0; j < 8; j++) {
                mx0 = fmaxf(mx0, fmaxf(sacc[j][0], sacc[j][1]));
                mx1 = fmaxf(mx1, fmaxf(sacc[j][2], sacc[j][3]));
            }
            mx0 = fmaxf(mx0, __shfl_xor_sync(0xffffffffu, mx0, 1));
            mx0 = fmaxf(mx0, __shfl_xor_sync(0xffffffffu, mx0, 2));
            mx1 = fmaxf(mx1, __shfl_xor_sync(0xffffffffu, mx1, 1));
            mx1 = fmaxf(mx1, __shfl_xor_sync(0xffffffffu, mx1, 2));

            const float sc0 = ex2f((m0 - mx0) * LOG2E);
            const float sc1 = ex2f((m1 - mx1) * LOG2E);
            float la0 = 0.f, la1 = 0.f;
#pragma unroll
            for (int j = 0; j < 8; j++) {
                float p0 = (sacc[j][0] > -1e29f) ? ex2f((sacc[j][0] - mx0) * LOG2E) : 0.f;
                float p1 = (sacc[j][1] > -1e29f) ? ex2f((sacc[j][1] - mx0) * LOG2E) : 0.f;
                float p2 = (sacc[j][2] > -1e29f) ? ex2f((sacc[j][2] - mx1) * LOG2E) : 0.f;
                float p3 = (sacc[j][3] > -1e29f) ? ex2f((sacc[j][3] - mx1) * LOG2E) : 0.f;
                sacc[j][0] = p0; sacc[j][1] = p1; sacc[j][2] = p2; sacc[j][3] = p3;
                la0 += p0 + p1;
                la1 += p2 + p3;
            }
            la0 += __shfl_xor_sync(0xffffffffu, la0, 1);
            la0 += __shfl_xor_sync(0xffffffffu, la0, 2);
            la1 += __shfl_xor_sync(0xffffffffu, la1, 1);
            la1 += __shfl_xor_sync(0xffffffffu, la1, 2);
            l0 = l0 * sc0 + la0;
            l1 = l1 * sc1 + la1;
            m0 = mx0; m1 = mx1;

#pragma unroll
            for (int nf = 0; nf < 16; nf++) {
                oacc[nf][0] *= sc0; oacc[nf][1] *= sc0;
                oacc[nf][2] *= sc1; oacc[nf][3] *= sc1;
            }

#pragma unroll
            for (int s4 = 0; s4 < 4; s4++) {
                uint32_t ah[4];
                ah[0] = pack_h(sacc[2 * s4][0],     sacc[2 * s4][1]);
                ah[1] = pack_h(sacc[2 * s4][2],     sacc[2 * s4][3]);
                ah[2] = pack_h(sacc[2 * s4 + 1][0], sacc[2 * s4 + 1][1]);
                ah[3] = pack_h(sacc[2 * s4 + 1][2], sacc[2 * s4 + 1][3]);

                const uint32_t vbase = stb + 2 * AMAT * 2 + vrow_off +
                                       (uint32_t)(s4 * 16 * AT_PAD) * 2;
#pragma unroll
                for (int db = 0; db < 8; db++) {
                    uint32_t vh[4];
                    ldsm4t(vh, vbase + db * 32);
                    mma_h_f32(oacc[2 * db],     ah, vh);
                    mma_h_f32(oacc[2 * db + 1], ah, &vh[2]);
                }
            }
        }
        __syncthreads();
    }
#undef LOAD_KV

    const float inv0 = 1.f / l0;
    const float inv1 = 1.f / l1;
    const size_t o0 = (size_t)(b * S_ + qg0) * (NH_ * D_) + h * D_;
    const size_t o1 = (size_t)(b * S_ + qg1) * (NH_ * D_) + h * D_;
#pragma unroll
    for (int nf = 0; nf < 16; nf++) {
        const int dc = 8 * nf + 2 * (lane & 3);
        *(uint32_t*)(g_at_h + o0 + dc) =
            pack_h(oacc[nf][0] * inv0, oacc[nf][1] * inv0);
        *(uint32_t*)(g_at_h + o1 + dc) =
            pack_h(oacc[nf][2] * inv1, oacc[nf][3] * inv1);
    }
}

/* --------------------------------- launch --------------------------------- */
extern "C" void kernel_launch(void* const* d_in, const int* in_sizes, int n_in,
                              void* d_out, int out_size)
{
    const float* hidden = (const float*)d_in[0];
    const float* cosp   = (const float*)d_in[1];
    const float* sinp   = (const float*)d_in[2];
    const float* w_qkv  = (const float*)d_in[3];
    const float* b_qkv  = (const float*)d_in[4];
    const float* w_o    = (const float*)d_in[5];
    const float* b_o    = (const float*)d_in[6];
    float* out = (float*)d_out;

    __half *p_h_hi, *p_h_lo, *p_wq_hi, *p_wq_lo, *p_wo_h, *p_at_h;
    cudaGetSymbolAddress((void**)&p_h_hi, g_h_hi);
    cudaGetSymbolAddress((void**)&p_h_lo, g_h_lo);
    cudaGetSymbolAddress((void**)&p_wq_hi, g_wq_hi);
    cudaGetSymbolAddress((void**)&p_wq_lo, g_wq_lo);
    cudaGetSymbolAddress((void**)&p_wo_h, g_wo_h);
    cudaGetSymbolAddress((void**)&p_at_h, g_at_h);

    cudaFuncSetAttribute(gemm1_u,
                         cudaFuncAttributeMaxDynamicSharedMemorySize, G1_SMEM);
    cudaFuncSetAttribute(gemm_h1,
                         cudaFuncAttributeMaxDynamicSharedMemorySize, H1_SMEM);
    cudaFuncSetAttribute(attn_mma,
                         cudaFuncAttributeMaxDynamicSharedMemorySize, ATTN_SMEM_B);

    /* 0) all converts in one launch */
    cvt_all<<<(CV_N3 + 255) / 256, 256>>>(hidden, w_qkv, w_o);

    /* 1) dual-path qkv GEMM, fine 128x128 tiles */
    gemm1_u<<<dim3(QKV_OUT_ / 128, BS_ / 128), 256, G1_SMEM>>>(
        p_h_hi, p_h_lo, p_wq_hi, p_wq_lo, b_qkv, cosp, sinp, HID_);

    /* 2) flash attention (QK fp16x3, PV fp16x1, per-warp block skip) */
    attn_mma<<<dim3(S_ / 128, NH_, B_), 256, ATTN_SMEM_B>>>();

    /* 3) out = attn @ w_o^T + b_o (single-product fp16) */
    gemm_h1<<<dim3(HID_ / 256, BS_ / 128), 512, H1_SMEM>>>(
        p_at_h, p_wo_h, b_o, out, HID_, HID_);
}